// round 1
// baseline (speedup 1.0000x reference)
#include <cuda_runtime.h>
#include <math.h>

// Problem dims
#define Bn 2
#define Tn 1024
#define Cn 1024
#define Hn 16
#define Dn 64
#define BTn (Bn * Tn)
#define NTOK (Bn * Tn * Cn)
#define W_LR 64
#define A_LR 64
#define V_LR 64
#define G_LR 160
#define DECAY_SCALE (-0.6065306597126334f)
#define GN_EPS (64.0f * 1e-5f)

// ---------------- scratch (__device__ globals; no cudaMalloc allowed) ------
__device__ float g_xr[NTOK], g_xw[NTOK], g_xk[NTOK], g_xv[NTOK], g_xa[NTOK], g_xg[NTOK];
__device__ float g_r[NTOK], g_k0[NTOK], g_v[NTOK], g_w[NTOK], g_a[NTOK], g_g[NTOK];
__device__ float g_kk[NTOK], g_kf[NTOK];
__device__ float g_osc[NTOK], g_y[NTOK];
__device__ float g_tmpW[BTn * W_LR], g_tmpA[BTn * A_LR], g_tmpV[BTn * V_LR], g_tmpG[BTn * G_LR];

// ---------------- elementwise: token shift + 6 mixes -----------------------
__global__ void mix_kernel(const float* __restrict__ hs, const float* __restrict__ xmix) {
    int idx = blockIdx.x * blockDim.x + threadIdx.x;
    if (idx >= NTOK) return;
    int c = idx & (Cn - 1);
    int t = (idx / Cn) & (Tn - 1);
    float h = hs[idx];
    float prev = (t == 0) ? 0.f : hs[idx - Cn];
    float d = prev - h;
    g_xr[idx] = fmaf(d, xmix[0 * Cn + c], h);
    g_xw[idx] = fmaf(d, xmix[1 * Cn + c], h);
    g_xk[idx] = fmaf(d, xmix[2 * Cn + c], h);
    g_xv[idx] = fmaf(d, xmix[3 * Cn + c], h);
    g_xa[idx] = fmaf(d, xmix[4 * Cn + c], h);
    g_xg[idx] = fmaf(d, xmix[5 * Cn + c], h);
}

// ---------------- big GEMM: C[M,N] = A[M,K] * W[N,K]^T, 128x128x8 ----------
// Epilogues: 0 none, 3 sigmoid(x+bias), 4 DECAY*sigmoid(x+bias),
//            5 lerp: p1 + sigmoid(x+bias)*(p2-p1)
__device__ __forceinline__ float sigmoidf_(float x) { return 1.f / (1.f + expf(-x)); }

template <int EPI>
__global__ __launch_bounds__(256) void gemm128(
    const float* __restrict__ A, const float* __restrict__ Wt, float* __restrict__ Cm,
    int M, int N, int K,
    const float* __restrict__ bias, const float* __restrict__ p1, const float* __restrict__ p2) {
    __shared__ float As[8][128];
    __shared__ float Bs[8][128];
    const int tid = threadIdx.x;
    const int tx = tid & 15, ty = tid >> 4;
    const int row0 = blockIdx.y * 128, col0 = blockIdx.x * 128;
    const int arow = tid >> 1;
    const int acol = (tid & 1) * 4;
    const float* Aptr = A + (size_t)(row0 + arow) * K + acol;
    const float* Bptr = Wt + (size_t)(col0 + arow) * K + acol;
    float acc[8][8];
#pragma unroll
    for (int i = 0; i < 8; i++)
#pragma unroll
        for (int j = 0; j < 8; j++) acc[i][j] = 0.f;

    for (int k0 = 0; k0 < K; k0 += 8) {
        float4 av = *(const float4*)(Aptr + k0);
        float4 bv = *(const float4*)(Bptr + k0);
        As[acol + 0][arow] = av.x; As[acol + 1][arow] = av.y;
        As[acol + 2][arow] = av.z; As[acol + 3][arow] = av.w;
        Bs[acol + 0][arow] = bv.x; Bs[acol + 1][arow] = bv.y;
        Bs[acol + 2][arow] = bv.z; Bs[acol + 3][arow] = bv.w;
        __syncthreads();
#pragma unroll
        for (int kk = 0; kk < 8; kk++) {
            float af[8], bf[8];
#pragma unroll
            for (int i = 0; i < 8; i++) af[i] = As[kk][ty * 8 + i];
#pragma unroll
            for (int j = 0; j < 8; j++) bf[j] = Bs[kk][tx * 8 + j];
#pragma unroll
            for (int i = 0; i < 8; i++)
#pragma unroll
                for (int j = 0; j < 8; j++) acc[i][j] = fmaf(af[i], bf[j], acc[i][j]);
        }
        __syncthreads();
    }
#pragma unroll
    for (int i = 0; i < 8; i++) {
        int m = row0 + ty * 8 + i;
#pragma unroll
        for (int j = 0; j < 8; j++) {
            int n = col0 + tx * 8 + j;
            float x = acc[i][j];
            float val;
            if (EPI == 0) {
                val = x;
            } else if (EPI == 3) {
                val = sigmoidf_(x + bias[n]);
            } else if (EPI == 4) {
                val = DECAY_SCALE * sigmoidf_(x + bias[n]);
            } else { // 5: lerp with v_first
                size_t idx = (size_t)m * N + n;
                float s = sigmoidf_(x + bias[n]);
                float a = p1[idx], b = p2[idx];
                val = a + s * (b - a);
            }
            Cm[(size_t)m * N + n] = val;
        }
    }
}

// ---------------- small-N GEMM (LoRA stage 1): 64x64x16 --------------------
// Epilogues: 0 none, 1 tanh, 2 sigmoid
template <int EPI>
__global__ __launch_bounds__(256) void gemm64(
    const float* __restrict__ A, const float* __restrict__ Wt, float* __restrict__ Cm,
    int M, int N, int K) {
    __shared__ float As[16][64];
    __shared__ float Bs[16][64];
    const int tid = threadIdx.x;
    const int tx = tid & 15, ty = tid >> 4;
    const int row0 = blockIdx.y * 64, col0 = blockIdx.x * 64;
    const int arow = tid >> 2;
    const int acol = (tid & 3) * 4;
    const float* Aptr = A + (size_t)(row0 + arow) * K + acol;
    const int bn = col0 + arow;
    const float* Bptr = Wt + (size_t)bn * K + acol;
    float acc[4][4];
#pragma unroll
    for (int i = 0; i < 4; i++)
#pragma unroll
        for (int j = 0; j < 4; j++) acc[i][j] = 0.f;

    for (int k0 = 0; k0 < K; k0 += 16) {
        float4 av = *(const float4*)(Aptr + k0);
        float4 bv = make_float4(0.f, 0.f, 0.f, 0.f);
        if (bn < N) bv = *(const float4*)(Bptr + k0);
        As[acol + 0][arow] = av.x; As[acol + 1][arow] = av.y;
        As[acol + 2][arow] = av.z; As[acol + 3][arow] = av.w;
        Bs[acol + 0][arow] = bv.x; Bs[acol + 1][arow] = bv.y;
        Bs[acol + 2][arow] = bv.z; Bs[acol + 3][arow] = bv.w;
        __syncthreads();
#pragma unroll
        for (int kk = 0; kk < 16; kk++) {
            float af[4], bf[4];
#pragma unroll
            for (int i = 0; i < 4; i++) af[i] = As[kk][ty * 4 + i];
#pragma unroll
            for (int j = 0; j < 4; j++) bf[j] = Bs[kk][tx * 4 + j];
#pragma unroll
            for (int i = 0; i < 4; i++)
#pragma unroll
                for (int j = 0; j < 4; j++) acc[i][j] = fmaf(af[i], bf[j], acc[i][j]);
        }
        __syncthreads();
    }
#pragma unroll
    for (int i = 0; i < 4; i++) {
        int m = row0 + ty * 4 + i;
#pragma unroll
        for (int j = 0; j < 4; j++) {
            int n = col0 + tx * 4 + j;
            if (n < N) {
                float x = acc[i][j];
                float val;
                if (EPI == 0) val = x;
                else if (EPI == 1) val = tanhf(x);
                else val = sigmoidf_(x);
                Cm[(size_t)m * N + n] = val;
            }
        }
    }
}

// ---------------- kk normalize + final k -----------------------------------
__global__ void kkprep_kernel(const float* __restrict__ k_k, const float* __restrict__ k_a) {
    int gid = blockIdx.x * (blockDim.x >> 5) + (threadIdx.x >> 5);
    int lane = threadIdx.x & 31;
    if (gid >= Bn * Tn * Hn) return;
    size_t base = (size_t)gid * Dn;
    int h = gid & (Hn - 1);
    int c0 = h * Dn + lane, c1 = c0 + 32;
    float v0 = g_k0[base + lane], v1 = g_k0[base + lane + 32];
    float q0 = v0 * k_k[c0], q1 = v1 * k_k[c1];
    float s = q0 * q0 + q1 * q1;
#pragma unroll
    for (int off = 16; off > 0; off >>= 1) s += __shfl_xor_sync(0xffffffffu, s, off);
    float inv = 1.f / fmaxf(sqrtf(s), 1e-12f);
    g_kk[base + lane] = q0 * inv;
    g_kk[base + lane + 32] = q1 * inv;
    float a0 = g_a[base + lane], a1 = g_a[base + lane + 32];
    g_kf[base + lane] = v0 * (1.f + (a0 - 1.f) * k_a[c0]);
    g_kf[base + lane + 32] = v1 * (1.f + (a1 - 1.f) * k_a[c1]);
}

// ---------------- sequential WKV7 scan: one 256-thread block per (b,h) -----
// thread (dg,e): owns S[d in dg*16..dg*16+16)][e] in registers.
__global__ __launch_bounds__(256) void scan_kernel(float* __restrict__ out) {
    const int bh = blockIdx.x;            // 0..B*H-1
    const int b = bh / Hn, h = bh % Hn;
    const int tid = threadIdx.x;
    const int e = tid & 63;
    const int dg = tid >> 6;              // 0..3

    // shared: [buf][array][64]; arrays: 0=exp(w),1=k,2=v,3=r,4=kk,5=a
    __shared__ float sb[2][6][64];
    __shared__ float sred[4][64];
    __shared__ float sout[4][64];

    float S[16];
#pragma unroll
    for (int i = 0; i < 16; i++) S[i] = 0.f;

    const size_t base0 = ((size_t)b * Tn) * Cn + h * Dn;
    const float* ap = (dg == 0) ? g_w : (dg == 1) ? g_kf : (dg == 2) ? g_v : g_r;
    const float* ap2 = (dg == 0) ? g_kk : g_a;   // only tid<128 uses

    // prologue: load t=0
    {
        float x0 = ap[base0 + e];
        if (dg == 0) x0 = __expf(x0);
        sb[0][dg][e] = x0;
        if (tid < 128) sb[0][4 + dg][e] = ap2[base0 + e];
    }
    __syncthreads();

    for (int t = 0; t < Tn; t++) {
        const int cur = t & 1, nxt = cur ^ 1;
        // prefetch next step's arrays into registers
        float p0 = 0.f, p1 = 0.f;
        if (t + 1 < Tn) {
            size_t baseN = base0 + (size_t)(t + 1) * Cn;
            p0 = ap[baseN + e];
            if (dg == 0) p0 = __expf(p0);
            if (tid < 128) p1 = ap2[baseN + e];
        }
        // pass 1: decay + partial (kk^T S); also b = kk*a
        float ta_p = 0.f;
        float bcol[16];
#pragma unroll
        for (int i = 0; i < 16; i++) {
            int d = dg * 16 + i;
            float sv = S[i] * sb[cur][0][d];
            S[i] = sv;
            ta_p = fmaf(sb[cur][4][d], sv, ta_p);
            bcol[i] = sb[cur][4][d] * sb[cur][5][d];
        }
        sred[dg][e] = ta_p;
        if (t + 1 < Tn) {
            sb[nxt][dg][e] = p0;
            if (tid < 128) sb[nxt][4 + dg][e] = p1;
        }
        __syncthreads();
        // pass 2: rank-1 updates + output partial
        float ta = -(sred[0][e] + sred[1][e] + sred[2][e] + sred[3][e]);
        float ve = sb[cur][2][e];
        float outp = 0.f;
#pragma unroll
        for (int i = 0; i < 16; i++) {
            int d = dg * 16 + i;
            float sv = fmaf(bcol[i], ta, S[i]);
            sv = fmaf(sb[cur][1][d], ve, sv);
            S[i] = sv;
            outp = fmaf(sb[cur][3][d], sv, outp);
        }
        sout[dg][e] = outp;
        __syncthreads();
        if (dg == 0) {
            out[base0 + (size_t)t * Cn + e] =
                sout[0][e] + sout[1][e] + sout[2][e] + sout[3][e];
        }
    }
}

// ---------------- GroupNorm + corr + gate ----------------------------------
__global__ void post_kernel(const float* __restrict__ r_k, const float* __restrict__ gn_w,
                            const float* __restrict__ gn_b) {
    int gid = blockIdx.x * (blockDim.x >> 5) + (threadIdx.x >> 5);
    int lane = threadIdx.x & 31;
    if (gid >= Bn * Tn * Hn) return;
    size_t base = (size_t)gid * Dn;
    int h = gid & (Hn - 1);
    int c0 = h * Dn + lane, c1 = c0 + 32;
    float o0 = g_osc[base + lane], o1 = g_osc[base + lane + 32];
    float s1 = o0 + o1;
    float s2 = o0 * o0 + o1 * o1;
    float rr0 = g_r[base + lane], rr1 = g_r[base + lane + 32];
    float kk0 = g_kf[base + lane], kk1 = g_kf[base + lane + 32];
    float dp = rr0 * kk0 * r_k[c0] + rr1 * kk1 * r_k[c1];
#pragma unroll
    for (int off = 16; off > 0; off >>= 1) {
        s1 += __shfl_xor_sync(0xffffffffu, s1, off);
        s2 += __shfl_xor_sync(0xffffffffu, s2, off);
        dp += __shfl_xor_sync(0xffffffffu, dp, off);
    }
    float mu = s1 * (1.f / 64.f);
    float var = s2 * (1.f / 64.f) - mu * mu;
    float inv = 1.f / sqrtf(var + GN_EPS);
    float v0 = g_v[base + lane], v1 = g_v[base + lane + 32];
    float y0 = ((o0 - mu) * inv * gn_w[c0] + gn_b[c0] + dp * v0) * g_g[base + lane];
    float y1 = ((o1 - mu) * inv * gn_w[c1] + gn_b[c1] + dp * v1) * g_g[base + lane + 32];
    g_y[base + lane] = y0;
    g_y[base + lane + 32] = y1;
}

// ---------------- launch ----------------------------------------------------
extern "C" void kernel_launch(void* const* d_in, const int* in_sizes, int n_in,
                              void* d_out, int out_size) {
    const float* hs     = (const float*)d_in[0];
    const float* vfirst = (const float*)d_in[1];
    const float* xmix   = (const float*)d_in[2];
    const float* k_k    = (const float*)d_in[3];
    const float* k_a    = (const float*)d_in[4];
    const float* r_k    = (const float*)d_in[5];
    const float* W_r    = (const float*)d_in[6];
    const float* W_k    = (const float*)d_in[7];
    const float* W_v    = (const float*)d_in[8];
    const float* W_o    = (const float*)d_in[9];
    const float* w_A    = (const float*)d_in[10];
    const float* w_B    = (const float*)d_in[11];
    const float* w_b    = (const float*)d_in[12];
    const float* a_A    = (const float*)d_in[13];
    const float* a_B    = (const float*)d_in[14];
    const float* a_b    = (const float*)d_in[15];
    const float* v_A    = (const float*)d_in[16];
    const float* v_B    = (const float*)d_in[17];
    const float* v_b    = (const float*)d_in[18];
    const float* g_A    = (const float*)d_in[19];
    const float* g_B    = (const float*)d_in[20];
    const float* gn_w   = (const float*)d_in[21];
    const float* gn_b   = (const float*)d_in[22];
    float* outp = (float*)d_out;

    // device pointers to __device__ globals
    float *p_xr, *p_xw, *p_xk, *p_xv, *p_xa, *p_xg;
    float *p_r, *p_k0, *p_v, *p_w, *p_a, *p_g, *p_osc, *p_y;
    float *p_tmpW, *p_tmpA, *p_tmpV, *p_tmpG;
    cudaGetSymbolAddress((void**)&p_xr, g_xr);
    cudaGetSymbolAddress((void**)&p_xw, g_xw);
    cudaGetSymbolAddress((void**)&p_xk, g_xk);
    cudaGetSymbolAddress((void**)&p_xv, g_xv);
    cudaGetSymbolAddress((void**)&p_xa, g_xa);
    cudaGetSymbolAddress((void**)&p_xg, g_xg);
    cudaGetSymbolAddress((void**)&p_r, g_r);
    cudaGetSymbolAddress((void**)&p_k0, g_k0);
    cudaGetSymbolAddress((void**)&p_v, g_v);
    cudaGetSymbolAddress((void**)&p_w, g_w);
    cudaGetSymbolAddress((void**)&p_a, g_a);
    cudaGetSymbolAddress((void**)&p_g, g_g);
    cudaGetSymbolAddress((void**)&p_osc, g_osc);
    cudaGetSymbolAddress((void**)&p_y, g_y);
    cudaGetSymbolAddress((void**)&p_tmpW, g_tmpW);
    cudaGetSymbolAddress((void**)&p_tmpA, g_tmpA);
    cudaGetSymbolAddress((void**)&p_tmpV, g_tmpV);
    cudaGetSymbolAddress((void**)&p_tmpG, g_tmpG);

    // 1. token shift + mixes
    mix_kernel<<<(NTOK + 255) / 256, 256>>>(hs, xmix);

    dim3 gBig(Cn / 128, BTn / 128);   // (8, 16)
    // 2-4. r, k0, v0
    gemm128<0><<<gBig, 256>>>(p_xr, W_r, p_r, BTn, Cn, Cn, nullptr, nullptr, nullptr);
    gemm128<0><<<gBig, 256>>>(p_xk, W_k, p_k0, BTn, Cn, Cn, nullptr, nullptr, nullptr);
    gemm128<0><<<gBig, 256>>>(p_xv, W_v, p_v, BTn, Cn, Cn, nullptr, nullptr, nullptr);

    // 5-6. w LoRA: tanh stage then DECAY*sigmoid(x + w_b)
    gemm64<1><<<dim3(1, BTn / 64), 256>>>(p_xw, w_A, p_tmpW, BTn, W_LR, Cn);
    gemm128<4><<<gBig, 256>>>(p_tmpW, w_B, p_w, BTn, Cn, W_LR, w_b, nullptr, nullptr);

    // 7-8. a LoRA
    gemm64<0><<<dim3(1, BTn / 64), 256>>>(p_xa, a_A, p_tmpA, BTn, A_LR, Cn);
    gemm128<3><<<gBig, 256>>>(p_tmpA, a_B, p_a, BTn, Cn, A_LR, a_b, nullptr, nullptr);

    // 9-10. v LoRA + lerp with v_first (in place over p_v as p1)
    gemm64<0><<<dim3(1, BTn / 64), 256>>>(p_xv, v_A, p_tmpV, BTn, V_LR, Cn);
    gemm128<5><<<gBig, 256>>>(p_tmpV, v_B, p_v, BTn, Cn, V_LR, v_b, p_v, vfirst);

    // 11-12. g LoRA
    gemm64<2><<<dim3((G_LR + 63) / 64, BTn / 64), 256>>>(p_xg, g_A, p_tmpG, BTn, G_LR, Cn);
    gemm128<0><<<gBig, 256>>>(p_tmpG, g_B, p_g, BTn, Cn, G_LR, nullptr, nullptr, nullptr);

    // 13. kk normalize + final k (needs k0, a)
    kkprep_kernel<<<(Bn * Tn * Hn + 7) / 8, 256>>>(k_k, k_a);

    // 14. sequential scan
    scan_kernel<<<Bn * Hn, 256>>>(p_osc);

    // 15. groupnorm + corr + gate
    post_kernel<<<(Bn * Tn * Hn + 7) / 8, 256>>>(r_k, gn_w, gn_b);

    // 16. output projection
    gemm128<0><<<gBig, 256>>>(p_y, W_o, outp, BTn, Cn, Cn, nullptr, nullptr, nullptr);
}

// round 2
// speedup vs baseline: 1.8332x; 1.8332x over previous
#include <cuda_runtime.h>
#include <math.h>
#include <stdint.h>

// Problem dims
#define Bn 2
#define Tn 1024
#define Cn 1024
#define Hn 16
#define Dn 64
#define BTn (Bn * Tn)
#define NTOK (Bn * Tn * Cn)
#define W_LR 64
#define A_LR 64
#define V_LR 64
#define G_LR 160
#define DECAY_SCALE (-0.6065306597126334f)
#define GN_EPS (64.0f * 1e-5f)

// tf32 weight scratch offsets
#define OFF_Wr 0
#define OFF_Wk 1048576
#define OFF_Wv 2097152
#define OFF_Wo 3145728
#define OFF_wA 4194304
#define OFF_aA 4259840
#define OFF_vA 4325376
#define OFF_gA 4390912
#define OFF_wB 4554752
#define OFF_aB 4620288
#define OFF_vB 4685824
#define OFF_gB 4751360
#define WTS_TOTAL 4915200

// ---------------- scratch (__device__ globals) -----------------------------
__device__ float g_xr[NTOK], g_xw[NTOK], g_xk[NTOK], g_xv[NTOK], g_xa[NTOK], g_xg[NTOK];
__device__ float g_r[NTOK], g_k0[NTOK], g_v[NTOK], g_w[NTOK], g_a[NTOK], g_g[NTOK];
__device__ float g_kk[NTOK], g_kf[NTOK];
__device__ float g_osc[NTOK], g_y[NTOK];
__device__ float g_tmpW[BTn * W_LR], g_tmpA[BTn * A_LR], g_tmpV[BTn * V_LR], g_tmpG[BTn * G_LR];
__device__ float g_wts[WTS_TOTAL];

// ---------------- helpers --------------------------------------------------
__device__ __forceinline__ float sigmoidf_(float x) { return 1.f / (1.f + expf(-x)); }

__device__ __forceinline__ float to_tf32(float x) {
    uint32_t u;
    asm("cvt.rna.tf32.f32 %0, %1;" : "=r"(u) : "f"(x));
    return __uint_as_float(u);
}

__device__ __forceinline__ void cpasync16(void* smem, const void* gptr, int srcbytes) {
    uint32_t s = (uint32_t)__cvta_generic_to_shared(smem);
    asm volatile("cp.async.ca.shared.global [%0], [%1], 16, %2;" :: "r"(s), "l"(gptr), "r"(srcbytes));
}
__device__ __forceinline__ void cpcommit() { asm volatile("cp.async.commit_group;"); }
__device__ __forceinline__ void cpwait1() { asm volatile("cp.async.wait_group 1;"); }
__device__ __forceinline__ void cpwait0() { asm volatile("cp.async.wait_group 0;"); }

__device__ __forceinline__ void mma_tf32(float* d, const uint32_t* a, const uint32_t* b) {
    asm volatile(
        "mma.sync.aligned.m16n8k8.row.col.f32.tf32.tf32.f32 "
        "{%0,%1,%2,%3}, {%4,%5,%6,%7}, {%8,%9}, {%0,%1,%2,%3};"
        : "+f"(d[0]), "+f"(d[1]), "+f"(d[2]), "+f"(d[3])
        : "r"(a[0]), "r"(a[1]), "r"(a[2]), "r"(a[3]), "r"(b[0]), "r"(b[1]));
}

// ---------------- mix + weight tf32 conversion (one launch) ----------------
__global__ void mixcvt_kernel(const float* __restrict__ hs, const float* __restrict__ xmix,
                              const float* __restrict__ Wr, const float* __restrict__ Wk,
                              const float* __restrict__ Wv, const float* __restrict__ Wo,
                              const float* __restrict__ wA, const float* __restrict__ aA,
                              const float* __restrict__ vA, const float* __restrict__ gA,
                              const float* __restrict__ wB, const float* __restrict__ aB,
                              const float* __restrict__ vB, const float* __restrict__ gB) {
    int idx = blockIdx.x * blockDim.x + threadIdx.x;
    if (idx < NTOK) {
        int c = idx & (Cn - 1);
        int t = (idx / Cn) & (Tn - 1);
        float h = hs[idx];
        float prev = (t == 0) ? 0.f : hs[idx - Cn];
        float d = prev - h;
        g_xr[idx] = to_tf32(fmaf(d, xmix[0 * Cn + c], h));
        g_xw[idx] = to_tf32(fmaf(d, xmix[1 * Cn + c], h));
        g_xk[idx] = to_tf32(fmaf(d, xmix[2 * Cn + c], h));
        g_xv[idx] = to_tf32(fmaf(d, xmix[3 * Cn + c], h));
        g_xa[idx] = to_tf32(fmaf(d, xmix[4 * Cn + c], h));
        g_xg[idx] = to_tf32(fmaf(d, xmix[5 * Cn + c], h));
    } else {
        int j = idx - NTOK;
        if (j >= WTS_TOTAL) return;
        float v;
        if (j < OFF_Wk)      v = Wr[j - OFF_Wr];
        else if (j < OFF_Wv) v = Wk[j - OFF_Wk];
        else if (j < OFF_Wo) v = Wv[j - OFF_Wv];
        else if (j < OFF_wA) v = Wo[j - OFF_Wo];
        else if (j < OFF_aA) v = wA[j - OFF_wA];
        else if (j < OFF_vA) v = aA[j - OFF_aA];
        else if (j < OFF_gA) v = vA[j - OFF_vA];
        else if (j < OFF_wB) v = gA[j - OFF_gA];
        else if (j < OFF_aB) v = wB[j - OFF_wB];
        else if (j < OFF_vB) v = aB[j - OFF_aB];
        else if (j < OFF_gB) v = vB[j - OFF_vB];
        else                 v = gB[j - OFF_gB];
        g_wts[j] = to_tf32(v);
    }
}

// ---------------- tensor-core tf32 GEMM ------------------------------------
// C[M,N] = A[M,K] @ W[N,K]^T ; BM=128, BK=16, BN template (128 or 64).
// epi: 0 plain, 1 tanh+tf32, 2 sigmoid+tf32, 3 sigmoid(x+bias),
//      4 DECAY*sigmoid(x+bias), 5 lerp p1+(sig(x+bias))*(p2-p1), 6 tf32
struct Job {
    const float* A; const float* W; float* O;
    const float* bias; const float* p1; const float* p2;
    int epi;
};
struct Jobs { Job j[3]; };

template <int BN>
__global__ __launch_bounds__(256) void gemmTC(Jobs jobs, int N, int K) {
    constexpr int WARPS_N = BN / 32;        // 4 (BN=128) or 2 (BN=64)
    constexpr int WARPS_M = 8 / WARPS_N;    // 2 or 4
    constexpr int WM = 128 / WARPS_M;       // 64 or 32
    constexpr int MF = WM / 16;             // 4 or 2

    __shared__ float As[2][128][20];
    __shared__ float Bs[2][BN][20];

    Job jb = jobs.j[blockIdx.z];
    const int row0 = blockIdx.y * 128;
    const int col0 = blockIdx.x * BN;
    const int tid = threadIdx.x;
    const int wid = tid >> 5, lane = tid & 31;
    const int wm = wid % WARPS_M, wn = wid / WARPS_M;
    const int mbase = wm * WM, nbase = wn * 32;
    const int g = lane >> 2, q = lane & 3;
    const int arow = tid >> 2, ac4 = (tid & 3) * 4;

    float acc[MF][4][4];
#pragma unroll
    for (int i = 0; i < MF; i++)
#pragma unroll
        for (int j2 = 0; j2 < 4; j2++)
#pragma unroll
            for (int k2 = 0; k2 < 4; k2++) acc[i][j2][k2] = 0.f;

    const int nk = K >> 4;

    // prologue: tile 0
    {
        const float* Ag = jb.A + (size_t)(row0 + arow) * K + ac4;
        cpasync16(&As[0][arow][ac4], Ag, 16);
        cpasync16(&As[0][arow + 64][ac4], Ag + (size_t)64 * K, 16);
        int bn0 = col0 + arow;
        const float* Bg = jb.W + (size_t)bn0 * K + ac4;
        cpasync16(&Bs[0][arow][ac4], Bg, (bn0 < N) ? 16 : 0);
        if (BN == 128)
            cpasync16(&Bs[0][arow + 64][ac4], Bg + (size_t)64 * K, (bn0 + 64 < N) ? 16 : 0);
        cpcommit();
    }

    for (int kt = 0; kt < nk; kt++) {
        const int buf = kt & 1;
        if (kt + 1 < nk) {
            const int nb = buf ^ 1;
            const float* Ag = jb.A + (size_t)(row0 + arow) * K + (kt + 1) * 16 + ac4;
            cpasync16(&As[nb][arow][ac4], Ag, 16);
            cpasync16(&As[nb][arow + 64][ac4], Ag + (size_t)64 * K, 16);
            int bn0 = col0 + arow;
            const float* Bg = jb.W + (size_t)bn0 * K + (kt + 1) * 16 + ac4;
            cpasync16(&Bs[nb][arow][ac4], Bg, (bn0 < N) ? 16 : 0);
            if (BN == 128)
                cpasync16(&Bs[nb][arow + 64][ac4], Bg + (size_t)64 * K, (bn0 + 64 < N) ? 16 : 0);
            cpcommit();
            cpwait1();
        } else {
            cpwait0();
        }
        __syncthreads();

        const uint32_t* Au = (const uint32_t*)&As[buf][0][0];
        const uint32_t* Bu = (const uint32_t*)&Bs[buf][0][0];
#pragma unroll
        for (int ks = 0; ks < 16; ks += 8) {
            uint32_t af[MF][4], bf[4][2];
#pragma unroll
            for (int mf = 0; mf < MF; mf++) {
                int m = mbase + mf * 16 + g;
                af[mf][0] = Au[m * 20 + ks + q];
                af[mf][1] = Au[(m + 8) * 20 + ks + q];
                af[mf][2] = Au[m * 20 + ks + q + 4];
                af[mf][3] = Au[(m + 8) * 20 + ks + q + 4];
            }
#pragma unroll
            for (int nf = 0; nf < 4; nf++) {
                int n = nbase + nf * 8 + g;
                bf[nf][0] = Bu[n * 20 + ks + q];
                bf[nf][1] = Bu[n * 20 + ks + q + 4];
            }
#pragma unroll
            for (int mf = 0; mf < MF; mf++)
#pragma unroll
                for (int nf = 0; nf < 4; nf++) mma_tf32(acc[mf][nf], af[mf], bf[nf]);
        }
        __syncthreads();
    }

    // epilogue
    const int epi = jb.epi;
#pragma unroll
    for (int mf = 0; mf < MF; mf++) {
#pragma unroll
        for (int nf = 0; nf < 4; nf++) {
            int r0 = row0 + mbase + mf * 16 + g;
            int c = col0 + nbase + nf * 8 + 2 * q;
            if (c >= N) continue;
#pragma unroll
            for (int rr = 0; rr < 2; rr++) {
                int r = r0 + rr * 8;
                float x0 = acc[mf][nf][rr * 2 + 0];
                float x1 = acc[mf][nf][rr * 2 + 1];
                float y0, y1;
                if (epi == 0) { y0 = x0; y1 = x1; }
                else if (epi == 6) { y0 = to_tf32(x0); y1 = to_tf32(x1); }
                else if (epi == 1) { y0 = to_tf32(tanhf(x0)); y1 = to_tf32(tanhf(x1)); }
                else if (epi == 2) { y0 = to_tf32(sigmoidf_(x0)); y1 = to_tf32(sigmoidf_(x1)); }
                else if (epi == 3) {
                    y0 = sigmoidf_(x0 + __ldg(jb.bias + c));
                    y1 = sigmoidf_(x1 + __ldg(jb.bias + c + 1));
                } else if (epi == 4) {
                    y0 = DECAY_SCALE * sigmoidf_(x0 + __ldg(jb.bias + c));
                    y1 = DECAY_SCALE * sigmoidf_(x1 + __ldg(jb.bias + c + 1));
                } else { // 5
                    size_t i0 = (size_t)r * N + c;
                    float s0 = sigmoidf_(x0 + __ldg(jb.bias + c));
                    float s1 = sigmoidf_(x1 + __ldg(jb.bias + c + 1));
                    float a0 = jb.p1[i0], b0 = jb.p2[i0];
                    float a1 = jb.p1[i0 + 1], b1 = jb.p2[i0 + 1];
                    y0 = fmaf(s0, b0 - a0, a0);
                    y1 = fmaf(s1, b1 - a1, a1);
                }
                *(float2*)(jb.O + (size_t)r * N + c) = make_float2(y0, y1);
            }
        }
    }
}

// ---------------- kk normalize + final k -----------------------------------
__global__ void kkprep_kernel(const float* __restrict__ k_k, const float* __restrict__ k_a) {
    int gid = blockIdx.x * (blockDim.x >> 5) + (threadIdx.x >> 5);
    int lane = threadIdx.x & 31;
    if (gid >= Bn * Tn * Hn) return;
    size_t base = (size_t)gid * Dn;
    int h = gid & (Hn - 1);
    int c0 = h * Dn + lane, c1 = c0 + 32;
    float v0 = g_k0[base + lane], v1 = g_k0[base + lane + 32];
    float q0 = v0 * k_k[c0], q1 = v1 * k_k[c1];
    float s = q0 * q0 + q1 * q1;
#pragma unroll
    for (int off = 16; off > 0; off >>= 1) s += __shfl_xor_sync(0xffffffffu, s, off);
    float inv = 1.f / fmaxf(sqrtf(s), 1e-12f);
    g_kk[base + lane] = q0 * inv;
    g_kk[base + lane + 32] = q1 * inv;
    float a0 = g_a[base + lane], a1 = g_a[base + lane + 32];
    g_kf[base + lane] = v0 * (1.f + (a0 - 1.f) * k_a[c0]);
    g_kf[base + lane + 32] = v1 * (1.f + (a1 - 1.f) * k_a[c1]);
}

// ---------------- sequential WKV7 scan -------------------------------------
__global__ __launch_bounds__(256) void scan_kernel(float* __restrict__ out) {
    const int bh = blockIdx.x;
    const int b = bh / Hn, h = bh % Hn;
    const int tid = threadIdx.x;
    const int e = tid & 63;
    const int dg = tid >> 6;

    __shared__ float sb[2][6][64];
    __shared__ float sred[4][64];
    __shared__ float sout[4][64];

    float S[16];
#pragma unroll
    for (int i = 0; i < 16; i++) S[i] = 0.f;

    const size_t base0 = ((size_t)b * Tn) * Cn + h * Dn;
    const float* ap = (dg == 0) ? g_w : (dg == 1) ? g_kf : (dg == 2) ? g_v : g_r;
    const float* ap2 = (dg == 0) ? g_kk : g_a;

    // prologue: t=0 into sb[0]; t=1 into hold regs
    {
        float x0 = ap[base0 + e];
        if (dg == 0) x0 = __expf(x0);
        sb[0][dg][e] = x0;
        if (tid < 128) sb[0][4 + dg][e] = ap2[base0 + e];
    }
    float h0 = 0.f, h1 = 0.f;
    {
        size_t b1 = base0 + Cn;
        h0 = __ldg(ap + b1 + e);
        if (tid < 128) h1 = __ldg(ap2 + b1 + e);
    }
    __syncthreads();

    for (int t = 0; t < Tn; t++) {
        const int cur = t & 1, nxt = cur ^ 1;
        // issue loads for t+2
        float n0 = 0.f, n1 = 0.f;
        if (t + 2 < Tn) {
            size_t b2 = base0 + (size_t)(t + 2) * Cn;
            n0 = __ldg(ap + b2 + e);
            if (tid < 128) n1 = __ldg(ap2 + b2 + e);
        }
        // pass 1: decay + partial (kk^T S); b = kk*a
        float ta_a = 0.f, ta_b = 0.f;
        float bcol[16];
#pragma unroll
        for (int i = 0; i < 16; i += 2) {
            int d = dg * 16 + i;
            float sv0 = S[i] * sb[cur][0][d];
            float sv1 = S[i + 1] * sb[cur][0][d + 1];
            S[i] = sv0; S[i + 1] = sv1;
            ta_a = fmaf(sb[cur][4][d], sv0, ta_a);
            ta_b = fmaf(sb[cur][4][d + 1], sv1, ta_b);
            bcol[i] = sb[cur][4][d] * sb[cur][5][d];
            bcol[i + 1] = sb[cur][4][d + 1] * sb[cur][5][d + 1];
        }
        sred[dg][e] = ta_a + ta_b;
        // stage t+1 data (held from previous iteration)
        if (t + 1 < Tn) {
            float wv = h0;
            if (dg == 0) wv = __expf(wv);
            sb[nxt][dg][e] = wv;
            if (tid < 128) sb[nxt][4 + dg][e] = h1;
        }
        __syncthreads();
        // pass 2: rank-1 updates + output partial
        float ta = -(sred[0][e] + sred[1][e] + sred[2][e] + sred[3][e]);
        float ve = sb[cur][2][e];
        float out_a = 0.f, out_b = 0.f;
#pragma unroll
        for (int i = 0; i < 16; i += 2) {
            int d = dg * 16 + i;
            float sv0 = fmaf(bcol[i], ta, S[i]);
            float sv1 = fmaf(bcol[i + 1], ta, S[i + 1]);
            sv0 = fmaf(sb[cur][1][d], ve, sv0);
            sv1 = fmaf(sb[cur][1][d + 1], ve, sv1);
            S[i] = sv0; S[i + 1] = sv1;
            out_a = fmaf(sb[cur][3][d], sv0, out_a);
            out_b = fmaf(sb[cur][3][d + 1], sv1, out_b);
        }
        sout[dg][e] = out_a + out_b;
        __syncthreads();
        if (dg == 0) {
            out[base0 + (size_t)t * Cn + e] =
                sout[0][e] + sout[1][e] + sout[2][e] + sout[3][e];
        }
        h0 = n0; h1 = n1;
    }
}

// ---------------- GroupNorm + corr + gate ----------------------------------
__global__ void post_kernel(const float* __restrict__ r_k, const float* __restrict__ gn_w,
                            const float* __restrict__ gn_b) {
    int gid = blockIdx.x * (blockDim.x >> 5) + (threadIdx.x >> 5);
    int lane = threadIdx.x & 31;
    if (gid >= Bn * Tn * Hn) return;
    size_t base = (size_t)gid * Dn;
    int h = gid & (Hn - 1);
    int c0 = h * Dn + lane, c1 = c0 + 32;
    float o0 = g_osc[base + lane], o1 = g_osc[base + lane + 32];
    float s1 = o0 + o1;
    float s2 = o0 * o0 + o1 * o1;
    float rr0 = g_r[base + lane], rr1 = g_r[base + lane + 32];
    float kk0 = g_kf[base + lane], kk1 = g_kf[base + lane + 32];
    float dp = rr0 * kk0 * r_k[c0] + rr1 * kk1 * r_k[c1];
#pragma unroll
    for (int off = 16; off > 0; off >>= 1) {
        s1 += __shfl_xor_sync(0xffffffffu, s1, off);
        s2 += __shfl_xor_sync(0xffffffffu, s2, off);
        dp += __shfl_xor_sync(0xffffffffu, dp, off);
    }
    float mu = s1 * (1.f / 64.f);
    float var = s2 * (1.f / 64.f) - mu * mu;
    float inv = 1.f / sqrtf(var + GN_EPS);
    float v0 = g_v[base + lane], v1 = g_v[base + lane + 32];
    float y0 = ((o0 - mu) * inv * gn_w[c0] + gn_b[c0] + dp * v0) * g_g[base + lane];
    float y1 = ((o1 - mu) * inv * gn_w[c1] + gn_b[c1] + dp * v1) * g_g[base + lane + 32];
    g_y[base + lane] = to_tf32(y0);
    g_y[base + lane + 32] = to_tf32(y1);
}

// ---------------- launch ----------------------------------------------------
extern "C" void kernel_launch(void* const* d_in, const int* in_sizes, int n_in,
                              void* d_out, int out_size) {
    const float* hs     = (const float*)d_in[0];
    const float* vfirst = (const float*)d_in[1];
    const float* xmix   = (const float*)d_in[2];
    const float* k_k    = (const float*)d_in[3];
    const float* k_a    = (const float*)d_in[4];
    const float* r_k    = (const float*)d_in[5];
    const float* W_r    = (const float*)d_in[6];
    const float* W_k    = (const float*)d_in[7];
    const float* W_v    = (const float*)d_in[8];
    const float* W_o    = (const float*)d_in[9];
    const float* w_A    = (const float*)d_in[10];
    const float* w_B    = (const float*)d_in[11];
    const float* w_b    = (const float*)d_in[12];
    const float* a_A    = (const float*)d_in[13];
    const float* a_B    = (const float*)d_in[14];
    const float* a_b    = (const float*)d_in[15];
    const float* v_A    = (const float*)d_in[16];
    const float* v_B    = (const float*)d_in[17];
    const float* v_b    = (const float*)d_in[18];
    const float* g_Ain  = (const float*)d_in[19];
    const float* g_Bin  = (const float*)d_in[20];
    const float* gn_w   = (const float*)d_in[21];
    const float* gn_b   = (const float*)d_in[22];
    float* outp = (float*)d_out;

    float *p_xr, *p_xw, *p_xk, *p_xv, *p_xa, *p_xg;
    float *p_r, *p_k0, *p_v, *p_w, *p_a, *p_g, *p_osc, *p_y;
    float *p_tmpW, *p_tmpA, *p_tmpV, *p_tmpG, *p_wts;
    cudaGetSymbolAddress((void**)&p_xr, g_xr);
    cudaGetSymbolAddress((void**)&p_xw, g_xw);
    cudaGetSymbolAddress((void**)&p_xk, g_xk);
    cudaGetSymbolAddress((void**)&p_xv, g_xv);
    cudaGetSymbolAddress((void**)&p_xa, g_xa);
    cudaGetSymbolAddress((void**)&p_xg, g_xg);
    cudaGetSymbolAddress((void**)&p_r, g_r);
    cudaGetSymbolAddress((void**)&p_k0, g_k0);
    cudaGetSymbolAddress((void**)&p_v, g_v);
    cudaGetSymbolAddress((void**)&p_w, g_w);
    cudaGetSymbolAddress((void**)&p_a, g_a);
    cudaGetSymbolAddress((void**)&p_g, g_g);
    cudaGetSymbolAddress((void**)&p_osc, g_osc);
    cudaGetSymbolAddress((void**)&p_y, g_y);
    cudaGetSymbolAddress((void**)&p_tmpW, g_tmpW);
    cudaGetSymbolAddress((void**)&p_tmpA, g_tmpA);
    cudaGetSymbolAddress((void**)&p_tmpV, g_tmpV);
    cudaGetSymbolAddress((void**)&p_tmpG, g_tmpG);
    cudaGetSymbolAddress((void**)&p_wts, g_wts);

    // 1. mix + weight tf32 conversion
    {
        int total = NTOK + WTS_TOTAL;
        mixcvt_kernel<<<(total + 255) / 256, 256>>>(hs, xmix, W_r, W_k, W_v, W_o,
                                                    w_A, a_A, v_A, g_Ain,
                                                    w_B, a_B, v_B, g_Bin);
    }

    // 2. r, k0, v0 (z=3)
    {
        Jobs J;
        J.j[0] = { p_xr, p_wts + OFF_Wr, p_r,  nullptr, nullptr, nullptr, 0 };
        J.j[1] = { p_xk, p_wts + OFF_Wk, p_k0, nullptr, nullptr, nullptr, 0 };
        J.j[2] = { p_xv, p_wts + OFF_Wv, p_v,  nullptr, nullptr, nullptr, 0 };
        gemmTC<128><<<dim3(8, 16, 3), 256>>>(J, Cn, Cn);
    }
    // 3. LoRA stage 1 for w,a,v (z=3)
    {
        Jobs J;
        J.j[0] = { p_xw, p_wts + OFF_wA, p_tmpW, nullptr, nullptr, nullptr, 1 };
        J.j[1] = { p_xa, p_wts + OFF_aA, p_tmpA, nullptr, nullptr, nullptr, 6 };
        J.j[2] = { p_xv, p_wts + OFF_vA, p_tmpV, nullptr, nullptr, nullptr, 6 };
        gemmTC<64><<<dim3(1, 16, 3), 256>>>(J, 64, Cn);
    }
    // 4. LoRA stage 2 for w,a,v (z=3)
    {
        Jobs J;
        J.j[0] = { p_tmpW, p_wts + OFF_wB, p_w, w_b, nullptr, nullptr, 4 };
        J.j[1] = { p_tmpA, p_wts + OFF_aB, p_a, a_b, nullptr, nullptr, 3 };
        J.j[2] = { p_tmpV, p_wts + OFF_vB, p_v, v_b, p_v, vfirst, 5 };
        gemmTC<128><<<dim3(8, 16, 3), 256>>>(J, Cn, 64);
    }
    // 5. kk normalize + final k
    kkprep_kernel<<<(Bn * Tn * Hn + 7) / 8, 256>>>(k_k, k_a);

    // 6. sequential scan  (ncu -s 5 -c 1 captures this launch)
    scan_kernel<<<Bn * Hn, 256>>>(p_osc);

    // 7. g LoRA stage 1
    {
        Jobs J;
        J.j[0] = { p_xg, p_wts + OFF_gA, p_tmpG, nullptr, nullptr, nullptr, 2 };
        J.j[1] = J.j[0]; J.j[2] = J.j[0];
        gemmTC<64><<<dim3(3, 16, 1), 256>>>(J, G_LR, Cn);
    }
    // 8. g LoRA stage 2
    {
        Jobs J;
        J.j[0] = { p_tmpG, p_wts + OFF_gB, p_g, nullptr, nullptr, nullptr, 0 };
        J.j[1] = J.j[0]; J.j[2] = J.j[0];
        gemmTC<128><<<dim3(8, 16, 1), 256>>>(J, Cn, G_LR);
    }
    // 9. groupnorm + corr + gate (tf32 output for o-proj)
    post_kernel<<<(Bn * Tn * Hn + 7) / 8, 256>>>(r_k, gn_w, gn_b);

    // 10. output projection
    {
        Jobs J;
        J.j[0] = { p_y, p_wts + OFF_Wo, outp, nullptr, nullptr, nullptr, 0 };
        J.j[1] = J.j[0]; J.j[2] = J.j[0];
        gemmTC<128><<<dim3(8, 16, 1), 256>>>(J, Cn, Cn);
    }
}

// round 3
// speedup vs baseline: 3.3905x; 1.8495x over previous
#include <cuda_runtime.h>
#include <math.h>
#include <stdint.h>

// Problem dims
#define Bn 2
#define Tn 1024
#define Cn 1024
#define Hn 16
#define Dn 64
#define BTn (Bn * Tn)
#define NTOK (Bn * Tn * Cn)
#define W_LR 64
#define A_LR 64
#define V_LR 64
#define G_LR 160
#define DECAY_SCALE (-0.6065306597126334f)
#define GN_EPS (64.0f * 1e-5f)
#define SS 8

// tf32 weight scratch offsets
#define OFF_Wr 0
#define OFF_Wk 1048576
#define OFF_Wv 2097152
#define OFF_Wo 3145728
#define OFF_wA 4194304
#define OFF_aA 4259840
#define OFF_vA 4325376
#define OFF_gA 4390912
#define OFF_wB 4554752
#define OFF_aB 4620288
#define OFF_vB 4685824
#define OFF_gB 4751360
#define WTS_TOTAL 4915200

// ---------------- scratch (__device__ globals) -----------------------------
__device__ float g_xr[NTOK], g_xw[NTOK], g_xk[NTOK], g_xv[NTOK], g_xa[NTOK], g_xg[NTOK];
__device__ float g_r[NTOK], g_k0[NTOK], g_v[NTOK], g_w[NTOK], g_a[NTOK], g_g[NTOK];
__device__ float g_kf[NTOK];
__device__ float g_m[NTOK], g_ad[NTOK], g_rd[NTOK], g_bb[NTOK];
__device__ float g_rb[BTn * Hn], g_rk[BTn * Hn];
__device__ float g_osc[NTOK], g_y[NTOK];
__device__ float g_tmpW[BTn * W_LR], g_tmpA[BTn * A_LR], g_tmpV[BTn * V_LR], g_tmpG[BTn * G_LR];
__device__ float g_wts[WTS_TOTAL];

// ---------------- helpers --------------------------------------------------
__device__ __forceinline__ float sigmoidf_(float x) { return 1.f / (1.f + expf(-x)); }

__device__ __forceinline__ float to_tf32(float x) {
    uint32_t u;
    asm("cvt.rna.tf32.f32 %0, %1;" : "=r"(u) : "f"(x));
    return __uint_as_float(u);
}

__device__ __forceinline__ void cpasync16(void* smem, const void* gptr, int srcbytes) {
    uint32_t s = (uint32_t)__cvta_generic_to_shared(smem);
    asm volatile("cp.async.ca.shared.global [%0], [%1], 16, %2;" :: "r"(s), "l"(gptr), "r"(srcbytes));
}
__device__ __forceinline__ void cpasync4(void* smem, const void* gptr) {
    uint32_t s = (uint32_t)__cvta_generic_to_shared(smem);
    asm volatile("cp.async.ca.shared.global [%0], [%1], 4;" :: "r"(s), "l"(gptr));
}
__device__ __forceinline__ void cpcommit() { asm volatile("cp.async.commit_group;"); }
__device__ __forceinline__ void cpwait1() { asm volatile("cp.async.wait_group 1;"); }
__device__ __forceinline__ void cpwait0() { asm volatile("cp.async.wait_group 0;"); }

__device__ __forceinline__ float2 ffma2(float2 a, float2 b, float2 c) {
    unsigned long long ua = *(unsigned long long*)&a;
    unsigned long long ub = *(unsigned long long*)&b;
    unsigned long long uc = *(unsigned long long*)&c;
    unsigned long long ud;
    asm("fma.rn.f32x2 %0, %1, %2, %3;" : "=l"(ud) : "l"(ua), "l"(ub), "l"(uc));
    return *(float2*)&ud;
}
__device__ __forceinline__ float2 fmul2(float2 a, float2 b) {
    unsigned long long ua = *(unsigned long long*)&a;
    unsigned long long ub = *(unsigned long long*)&b;
    unsigned long long ud;
    asm("mul.rn.f32x2 %0, %1, %2;" : "=l"(ud) : "l"(ua), "l"(ub));
    return *(float2*)&ud;
}

__device__ __forceinline__ void mma_tf32(float* d, const uint32_t* a, const uint32_t* b) {
    asm volatile(
        "mma.sync.aligned.m16n8k8.row.col.f32.tf32.tf32.f32 "
        "{%0,%1,%2,%3}, {%4,%5,%6,%7}, {%8,%9}, {%0,%1,%2,%3};"
        : "+f"(d[0]), "+f"(d[1]), "+f"(d[2]), "+f"(d[3])
        : "r"(a[0]), "r"(a[1]), "r"(a[2]), "r"(a[3]), "r"(b[0]), "r"(b[1]));
}

// ---------------- mix + weight tf32 conversion (one launch) ----------------
__global__ void mixcvt_kernel(const float* __restrict__ hs, const float* __restrict__ xmix,
                              const float* __restrict__ Wr, const float* __restrict__ Wk,
                              const float* __restrict__ Wv, const float* __restrict__ Wo,
                              const float* __restrict__ wA, const float* __restrict__ aA,
                              const float* __restrict__ vA, const float* __restrict__ gA,
                              const float* __restrict__ wB, const float* __restrict__ aB,
                              const float* __restrict__ vB, const float* __restrict__ gB) {
    int idx = blockIdx.x * blockDim.x + threadIdx.x;
    if (idx < NTOK) {
        int c = idx & (Cn - 1);
        int t = (idx / Cn) & (Tn - 1);
        float h = hs[idx];
        float prev = (t == 0) ? 0.f : hs[idx - Cn];
        float d = prev - h;
        g_xr[idx] = to_tf32(fmaf(d, xmix[0 * Cn + c], h));
        g_xw[idx] = to_tf32(fmaf(d, xmix[1 * Cn + c], h));
        g_xk[idx] = to_tf32(fmaf(d, xmix[2 * Cn + c], h));
        g_xv[idx] = to_tf32(fmaf(d, xmix[3 * Cn + c], h));
        g_xa[idx] = to_tf32(fmaf(d, xmix[4 * Cn + c], h));
        g_xg[idx] = to_tf32(fmaf(d, xmix[5 * Cn + c], h));
    } else {
        int j = idx - NTOK;
        if (j >= WTS_TOTAL) return;
        float v;
        if (j < OFF_Wk)      v = Wr[j - OFF_Wr];
        else if (j < OFF_Wv) v = Wk[j - OFF_Wk];
        else if (j < OFF_Wo) v = Wv[j - OFF_Wv];
        else if (j < OFF_wA) v = Wo[j - OFF_Wo];
        else if (j < OFF_aA) v = wA[j - OFF_wA];
        else if (j < OFF_vA) v = aA[j - OFF_aA];
        else if (j < OFF_gA) v = vA[j - OFF_vA];
        else if (j < OFF_wB) v = gA[j - OFF_gA];
        else if (j < OFF_aB) v = wB[j - OFF_wB];
        else if (j < OFF_vB) v = aB[j - OFF_aB];
        else if (j < OFF_gB) v = vB[j - OFF_vB];
        else                 v = gB[j - OFF_gB];
        g_wts[j] = to_tf32(v);
    }
}

// ---------------- tensor-core tf32 GEMM ------------------------------------
struct Job {
    const float* A; const float* W; float* O;
    const float* bias; const float* p1; const float* p2;
    int epi;
};
struct Jobs { Job j[3]; };

template <int BN>
__global__ __launch_bounds__(256) void gemmTC(Jobs jobs, int N, int K) {
    constexpr int WARPS_N = BN / 32;
    constexpr int WARPS_M = 8 / WARPS_N;
    constexpr int WM = 128 / WARPS_M;
    constexpr int MF = WM / 16;

    __shared__ float As[2][128][20];
    __shared__ float Bs[2][BN][20];

    Job jb = jobs.j[blockIdx.z];
    const int row0 = blockIdx.y * 128;
    const int col0 = blockIdx.x * BN;
    const int tid = threadIdx.x;
    const int wid = tid >> 5, lane = tid & 31;
    const int wm = wid % WARPS_M, wn = wid / WARPS_M;
    const int mbase = wm * WM, nbase = wn * 32;
    const int g = lane >> 2, q = lane & 3;
    const int arow = tid >> 2, ac4 = (tid & 3) * 4;

    float acc[MF][4][4];
#pragma unroll
    for (int i = 0; i < MF; i++)
#pragma unroll
        for (int j2 = 0; j2 < 4; j2++)
#pragma unroll
            for (int k2 = 0; k2 < 4; k2++) acc[i][j2][k2] = 0.f;

    const int nk = K >> 4;

    {
        const float* Ag = jb.A + (size_t)(row0 + arow) * K + ac4;
        cpasync16(&As[0][arow][ac4], Ag, 16);
        cpasync16(&As[0][arow + 64][ac4], Ag + (size_t)64 * K, 16);
        int bn0 = col0 + arow;
        const float* Bg = jb.W + (size_t)bn0 * K + ac4;
        cpasync16(&Bs[0][arow][ac4], Bg, (bn0 < N) ? 16 : 0);
        if (BN == 128)
            cpasync16(&Bs[0][arow + 64][ac4], Bg + (size_t)64 * K, (bn0 + 64 < N) ? 16 : 0);
        cpcommit();
    }

    for (int kt = 0; kt < nk; kt++) {
        const int buf = kt & 1;
        if (kt + 1 < nk) {
            const int nb = buf ^ 1;
            const float* Ag = jb.A + (size_t)(row0 + arow) * K + (kt + 1) * 16 + ac4;
            cpasync16(&As[nb][arow][ac4], Ag, 16);
            cpasync16(&As[nb][arow + 64][ac4], Ag + (size_t)64 * K, 16);
            int bn0 = col0 + arow;
            const float* Bg = jb.W + (size_t)bn0 * K + (kt + 1) * 16 + ac4;
            cpasync16(&Bs[nb][arow][ac4], Bg, (bn0 < N) ? 16 : 0);
            if (BN == 128)
                cpasync16(&Bs[nb][arow + 64][ac4], Bg + (size_t)64 * K, (bn0 + 64 < N) ? 16 : 0);
            cpcommit();
            cpwait1();
        } else {
            cpwait0();
        }
        __syncthreads();

        const uint32_t* Au = (const uint32_t*)&As[buf][0][0];
        const uint32_t* Bu = (const uint32_t*)&Bs[buf][0][0];
#pragma unroll
        for (int ks = 0; ks < 16; ks += 8) {
            uint32_t af[MF][4], bf[4][2];
#pragma unroll
            for (int mf = 0; mf < MF; mf++) {
                int m = mbase + mf * 16 + g;
                af[mf][0] = Au[m * 20 + ks + q];
                af[mf][1] = Au[(m + 8) * 20 + ks + q];
                af[mf][2] = Au[m * 20 + ks + q + 4];
                af[mf][3] = Au[(m + 8) * 20 + ks + q + 4];
            }
#pragma unroll
            for (int nf = 0; nf < 4; nf++) {
                int n = nbase + nf * 8 + g;
                bf[nf][0] = Bu[n * 20 + ks + q];
                bf[nf][1] = Bu[n * 20 + ks + q + 4];
            }
#pragma unroll
            for (int mf = 0; mf < MF; mf++)
#pragma unroll
                for (int nf = 0; nf < 4; nf++) mma_tf32(acc[mf][nf], af[mf], bf[nf]);
        }
        __syncthreads();
    }

    const int epi = jb.epi;
#pragma unroll
    for (int mf = 0; mf < MF; mf++) {
#pragma unroll
        for (int nf = 0; nf < 4; nf++) {
            int r0 = row0 + mbase + mf * 16 + g;
            int c = col0 + nbase + nf * 8 + 2 * q;
            if (c >= N) continue;
#pragma unroll
            for (int rr = 0; rr < 2; rr++) {
                int r = r0 + rr * 8;
                float x0 = acc[mf][nf][rr * 2 + 0];
                float x1 = acc[mf][nf][rr * 2 + 1];
                float y0, y1;
                if (epi == 0) { y0 = x0; y1 = x1; }
                else if (epi == 6) { y0 = to_tf32(x0); y1 = to_tf32(x1); }
                else if (epi == 1) { y0 = to_tf32(tanhf(x0)); y1 = to_tf32(tanhf(x1)); }
                else if (epi == 2) { y0 = to_tf32(sigmoidf_(x0)); y1 = to_tf32(sigmoidf_(x1)); }
                else if (epi == 3) {
                    y0 = sigmoidf_(x0 + __ldg(jb.bias + c));
                    y1 = sigmoidf_(x1 + __ldg(jb.bias + c + 1));
                } else if (epi == 4) {
                    y0 = DECAY_SCALE * sigmoidf_(x0 + __ldg(jb.bias + c));
                    y1 = DECAY_SCALE * sigmoidf_(x1 + __ldg(jb.bias + c + 1));
                } else {
                    size_t i0 = (size_t)r * N + c;
                    float s0 = sigmoidf_(x0 + __ldg(jb.bias + c));
                    float s1 = sigmoidf_(x1 + __ldg(jb.bias + c + 1));
                    float a0 = jb.p1[i0], b0 = jb.p2[i0];
                    float a1 = jb.p1[i0 + 1], b1 = jb.p2[i0 + 1];
                    y0 = fmaf(s0, b0 - a0, a0);
                    y1 = fmaf(s1, b1 - a1, a1);
                }
                *(float2*)(jb.O + (size_t)r * N + c) = make_float2(y0, y1);
            }
        }
    }
}

// ---------------- prep: kk-normalize, k-final, scan precomputes ------------
// per (b,t,h): m=exp(w), ad=-kk*m, rd=r*m, bb=kk*a, kf, rb=r.bb, rk=r.kf
__global__ void prep_kernel(const float* __restrict__ k_k, const float* __restrict__ k_a) {
    int gid = blockIdx.x * (blockDim.x >> 5) + (threadIdx.x >> 5);
    int lane = threadIdx.x & 31;
    if (gid >= BTn * Hn) return;
    int bt = gid >> 4, h = gid & 15;
    size_t base = (size_t)bt * Cn + h * Dn;
    int c0 = h * Dn + lane, c1 = c0 + 32;

    float k0a = g_k0[base + lane], k0b = g_k0[base + lane + 32];
    float q0 = k0a * k_k[c0], q1 = k0b * k_k[c1];
    float s = q0 * q0 + q1 * q1;
#pragma unroll
    for (int off = 16; off > 0; off >>= 1) s += __shfl_xor_sync(0xffffffffu, s, off);
    float inv = 1.f / fmaxf(sqrtf(s), 1e-12f);
    float kk0 = q0 * inv, kk1 = q1 * inv;

    float a0 = g_a[base + lane], a1 = g_a[base + lane + 32];
    float kf0 = k0a * (1.f + (a0 - 1.f) * k_a[c0]);
    float kf1 = k0b * (1.f + (a1 - 1.f) * k_a[c1]);
    float m0 = expf(g_w[base + lane]), m1 = expf(g_w[base + lane + 32]);
    float r0 = g_r[base + lane], r1 = g_r[base + lane + 32];
    float b0 = kk0 * a0, b1 = kk1 * a1;

    g_m[base + lane] = m0;          g_m[base + lane + 32] = m1;
    g_ad[base + lane] = -kk0 * m0;  g_ad[base + lane + 32] = -kk1 * m1;
    g_rd[base + lane] = r0 * m0;    g_rd[base + lane + 32] = r1 * m1;
    g_bb[base + lane] = b0;         g_bb[base + lane + 32] = b1;
    g_kf[base + lane] = kf0;        g_kf[base + lane + 32] = kf1;

    float rb = r0 * b0 + r1 * b1;
    float rk = r0 * kf0 + r1 * kf1;
#pragma unroll
    for (int off = 16; off > 0; off >>= 1) {
        rb += __shfl_xor_sync(0xffffffffu, rb, off);
        rk += __shfl_xor_sync(0xffffffffu, rk, off);
    }
    if (lane == 0) { g_rb[gid] = rb; g_rk[gid] = rk; }
}

// ---------------- sequential WKV7 scan, column-parallel ---------------------
// 64 blocks: block = (b,h,half). 128 threads: warp w covers 8 columns,
// lane = dq*8 + c, dq owns d in [dq*16, dq*16+16).  Column e = half*32+w*8+c.
// Per-step: ta = ad.S_old, ro = rd.S_old (warp-local shfl reduce over dq),
// out = ro + rb*ta + rk*v ; S = m*S + bb*ta + kf*v.   f32x2 packed math.
__global__ __launch_bounds__(128) void scan_kernel(float* __restrict__ out) {
    const int bx = blockIdx.x;
    const int bh = bx >> 1, half = bx & 1;
    const int b = bh >> 4, h = bh & 15;
    const int tid = threadIdx.x;
    const int wid = tid >> 5, lane = tid & 31;
    const int c = lane & 7, dq = lane >> 3;
    const int e = half * 32 + wid * 8 + c;
    const int d0 = dq * 16;
    const int bT0 = b * Tn;

    // staging: arrays 0..4 = m, ad, rd, bb, kf (full 64 d); v = 32 cols slice
    __shared__ float sb[2][5][SS][64];
    __shared__ float sv[2][SS][32];
    __shared__ float sc[2][2][SS];

    float2 S[8];
#pragma unroll
    for (int i = 0; i < 8; i++) S[i] = make_float2(0.f, 0.f);

    const float* aps[5] = { g_m, g_ad, g_rd, g_bb, g_kf };

    // stage lambda
    auto stage = [&](int ss, int bufI) {
#pragma unroll
        for (int j = tid; j < 704; j += 128) {
            if (j < 640) {
                int arr = j >> 7, rem = j & 127, s = rem >> 4, f4 = rem & 15;
                const float* src = aps[arr] + ((size_t)(bT0 + ss * SS + s)) * Cn + h * Dn + f4 * 4;
                cpasync16(&sb[bufI][arr][s][f4 * 4], src, 16);
            } else {
                int jj = j - 640;
                int s = jj >> 3, f4 = jj & 7;
                const float* src = g_v + ((size_t)(bT0 + ss * SS + s)) * Cn + h * Dn + half * 32 + f4 * 4;
                cpasync16(&sv[bufI][s][f4 * 4], src, 16);
            }
        }
        if (tid < 16) {
            int arr = tid >> 3, s = tid & 7;
            const float* src = (arr ? g_rk : g_rb) + (size_t)(bT0 + ss * SS + s) * Hn + h;
            cpasync4(&sc[bufI][arr][s], src);
        }
        cpcommit();
    };

    stage(0, 0);

    for (int ss = 0; ss < Tn / SS; ss++) {
        const int cur = ss & 1;
        cpwait0();
        __syncthreads();
        if (ss + 1 < Tn / SS) stage(ss + 1, cur ^ 1);

#pragma unroll
        for (int s = 0; s < SS; s++) {
            float4 m4[4], ad4[4], rd4[4], b4[4], k4[4];
#pragma unroll
            for (int i = 0; i < 4; i++) {
                m4[i]  = *(const float4*)&sb[cur][0][s][d0 + i * 4];
                ad4[i] = *(const float4*)&sb[cur][1][s][d0 + i * 4];
                rd4[i] = *(const float4*)&sb[cur][2][s][d0 + i * 4];
                b4[i]  = *(const float4*)&sb[cur][3][s][d0 + i * 4];
                k4[i]  = *(const float4*)&sb[cur][4][s][d0 + i * 4];
            }
            float v = sv[cur][s][wid * 8 + c];
            float rb = sc[cur][0][s], rk = sc[cur][1][s];

            const float2* m2 = (const float2*)m4;
            const float2* ad2 = (const float2*)ad4;
            const float2* rd2 = (const float2*)rd4;
            const float2* b2 = (const float2*)b4;
            const float2* k2 = (const float2*)k4;

            // two dots on old S, 2 accumulators each
            float2 tA = make_float2(0.f, 0.f), tB = make_float2(0.f, 0.f);
            float2 rA = make_float2(0.f, 0.f), rB = make_float2(0.f, 0.f);
#pragma unroll
            for (int i = 0; i < 8; i += 2) {
                tA = ffma2(ad2[i], S[i], tA);
                tB = ffma2(ad2[i + 1], S[i + 1], tB);
                rA = ffma2(rd2[i], S[i], rA);
                rB = ffma2(rd2[i + 1], S[i + 1], rB);
            }
            float ta = (tA.x + tB.x) + (tA.y + tB.y);
            float ro = (rA.x + rB.x) + (rA.y + rB.y);
            ta += __shfl_xor_sync(0xffffffffu, ta, 8);
            ro += __shfl_xor_sync(0xffffffffu, ro, 8);
            ta += __shfl_xor_sync(0xffffffffu, ta, 16);
            ro += __shfl_xor_sync(0xffffffffu, ro, 16);

            // update S and write out
            float2 ta2 = make_float2(ta, ta), v2 = make_float2(v, v);
#pragma unroll
            for (int i = 0; i < 8; i++) {
                float2 t1 = fmul2(k2[i], v2);
                t1 = ffma2(b2[i], ta2, t1);
                S[i] = ffma2(m2[i], S[i], t1);
            }
            if (dq == 0) {
                out[((size_t)(bT0 + ss * SS + s)) * Cn + h * Dn + e] =
                    fmaf(rb, ta, fmaf(rk, v, ro));
            }
        }
    }
}

// ---------------- GroupNorm + corr + gate ----------------------------------
__global__ void post_kernel(const float* __restrict__ r_k, const float* __restrict__ gn_w,
                            const float* __restrict__ gn_b) {
    int gid = blockIdx.x * (blockDim.x >> 5) + (threadIdx.x >> 5);
    int lane = threadIdx.x & 31;
    if (gid >= Bn * Tn * Hn) return;
    size_t base = (size_t)(gid >> 4) * Cn + (gid & 15) * Dn;
    int h = gid & 15;
    int c0 = h * Dn + lane, c1 = c0 + 32;
    float o0 = g_osc[base + lane], o1 = g_osc[base + lane + 32];
    float s1 = o0 + o1;
    float s2 = o0 * o0 + o1 * o1;
    float rr0 = g_r[base + lane], rr1 = g_r[base + lane + 32];
    float kk0 = g_kf[base + lane], kk1 = g_kf[base + lane + 32];
    float dp = rr0 * kk0 * r_k[c0] + rr1 * kk1 * r_k[c1];
#pragma unroll
    for (int off = 16; off > 0; off >>= 1) {
        s1 += __shfl_xor_sync(0xffffffffu, s1, off);
        s2 += __shfl_xor_sync(0xffffffffu, s2, off);
        dp += __shfl_xor_sync(0xffffffffu, dp, off);
    }
    float mu = s1 * (1.f / 64.f);
    float var = s2 * (1.f / 64.f) - mu * mu;
    float inv = 1.f / sqrtf(var + GN_EPS);
    float v0 = g_v[base + lane], v1 = g_v[base + lane + 32];
    float y0 = ((o0 - mu) * inv * gn_w[c0] + gn_b[c0] + dp * v0) * g_g[base + lane];
    float y1 = ((o1 - mu) * inv * gn_w[c1] + gn_b[c1] + dp * v1) * g_g[base + lane + 32];
    g_y[base + lane] = to_tf32(y0);
    g_y[base + lane + 32] = to_tf32(y1);
}

// ---------------- launch ----------------------------------------------------
extern "C" void kernel_launch(void* const* d_in, const int* in_sizes, int n_in,
                              void* d_out, int out_size) {
    const float* hs     = (const float*)d_in[0];
    const float* vfirst = (const float*)d_in[1];
    const float* xmix   = (const float*)d_in[2];
    const float* k_k    = (const float*)d_in[3];
    const float* k_a    = (const float*)d_in[4];
    const float* r_k    = (const float*)d_in[5];
    const float* W_r    = (const float*)d_in[6];
    const float* W_k    = (const float*)d_in[7];
    const float* W_v    = (const float*)d_in[8];
    const float* W_o    = (const float*)d_in[9];
    const float* w_A    = (const float*)d_in[10];
    const float* w_B    = (const float*)d_in[11];
    const float* w_b    = (const float*)d_in[12];
    const float* a_A    = (const float*)d_in[13];
    const float* a_B    = (const float*)d_in[14];
    const float* a_b    = (const float*)d_in[15];
    const float* v_A    = (const float*)d_in[16];
    const float* v_B    = (const float*)d_in[17];
    const float* v_b    = (const float*)d_in[18];
    const float* g_Ain  = (const float*)d_in[19];
    const float* g_Bin  = (const float*)d_in[20];
    const float* gn_w   = (const float*)d_in[21];
    const float* gn_b   = (const float*)d_in[22];
    float* outp = (float*)d_out;

    float *p_xr, *p_xw, *p_xk, *p_xv, *p_xa, *p_xg;
    float *p_r, *p_k0, *p_v, *p_w, *p_a, *p_g, *p_osc, *p_y;
    float *p_tmpW, *p_tmpA, *p_tmpV, *p_tmpG, *p_wts;
    cudaGetSymbolAddress((void**)&p_xr, g_xr);
    cudaGetSymbolAddress((void**)&p_xw, g_xw);
    cudaGetSymbolAddress((void**)&p_xk, g_xk);
    cudaGetSymbolAddress((void**)&p_xv, g_xv);
    cudaGetSymbolAddress((void**)&p_xa, g_xa);
    cudaGetSymbolAddress((void**)&p_xg, g_xg);
    cudaGetSymbolAddress((void**)&p_r, g_r);
    cudaGetSymbolAddress((void**)&p_k0, g_k0);
    cudaGetSymbolAddress((void**)&p_v, g_v);
    cudaGetSymbolAddress((void**)&p_w, g_w);
    cudaGetSymbolAddress((void**)&p_a, g_a);
    cudaGetSymbolAddress((void**)&p_g, g_g);
    cudaGetSymbolAddress((void**)&p_osc, g_osc);
    cudaGetSymbolAddress((void**)&p_y, g_y);
    cudaGetSymbolAddress((void**)&p_tmpW, g_tmpW);
    cudaGetSymbolAddress((void**)&p_tmpA, g_tmpA);
    cudaGetSymbolAddress((void**)&p_tmpV, g_tmpV);
    cudaGetSymbolAddress((void**)&p_tmpG, g_tmpG);
    cudaGetSymbolAddress((void**)&p_wts, g_wts);

    // 1. mix + weight tf32 conversion
    {
        int total = NTOK + WTS_TOTAL;
        mixcvt_kernel<<<(total + 255) / 256, 256>>>(hs, xmix, W_r, W_k, W_v, W_o,
                                                    w_A, a_A, v_A, g_Ain,
                                                    w_B, a_B, v_B, g_Bin);
    }

    // 2. r, k0, v0 (z=3)
    {
        Jobs J;
        J.j[0] = { p_xr, p_wts + OFF_Wr, p_r,  nullptr, nullptr, nullptr, 0 };
        J.j[1] = { p_xk, p_wts + OFF_Wk, p_k0, nullptr, nullptr, nullptr, 0 };
        J.j[2] = { p_xv, p_wts + OFF_Wv, p_v,  nullptr, nullptr, nullptr, 0 };
        gemmTC<128><<<dim3(8, 16, 3), 256>>>(J, Cn, Cn);
    }
    // 3. LoRA stage 1 for w,a,v (z=3)
    {
        Jobs J;
        J.j[0] = { p_xw, p_wts + OFF_wA, p_tmpW, nullptr, nullptr, nullptr, 1 };
        J.j[1] = { p_xa, p_wts + OFF_aA, p_tmpA, nullptr, nullptr, nullptr, 6 };
        J.j[2] = { p_xv, p_wts + OFF_vA, p_tmpV, nullptr, nullptr, nullptr, 6 };
        gemmTC<64><<<dim3(1, 16, 3), 256>>>(J, 64, Cn);
    }
    // 4. LoRA stage 2 for w,a,v (z=3)
    {
        Jobs J;
        J.j[0] = { p_tmpW, p_wts + OFF_wB, p_w, w_b, nullptr, nullptr, 4 };
        J.j[1] = { p_tmpA, p_wts + OFF_aB, p_a, a_b, nullptr, nullptr, 3 };
        J.j[2] = { p_tmpV, p_wts + OFF_vB, p_v, v_b, p_v, vfirst, 5 };
        gemmTC<128><<<dim3(8, 16, 3), 256>>>(J, Cn, 64);
    }
    // 5. prep (kk norm, k final, scan precomputes)
    prep_kernel<<<(BTn * Hn + 7) / 8, 256>>>(k_k, k_a);

    // 6. sequential scan
    scan_kernel<<<Bn * Hn * 2, 128>>>(p_osc);

    // 7. g LoRA stage 1
    {
        Jobs J;
        J.j[0] = { p_xg, p_wts + OFF_gA, p_tmpG, nullptr, nullptr, nullptr, 2 };
        J.j[1] = J.j[0]; J.j[2] = J.j[0];
        gemmTC<64><<<dim3(3, 16, 1), 256>>>(J, G_LR, Cn);
    }
    // 8. g LoRA stage 2
    {
        Jobs J;
        J.j[0] = { p_tmpG, p_wts + OFF_gB, p_g, nullptr, nullptr, nullptr, 0 };
        J.j[1] = J.j[0]; J.j[2] = J.j[0];
        gemmTC<128><<<dim3(8, 16, 1), 256>>>(J, Cn, G_LR);
    }
    // 9. groupnorm + corr + gate
    post_kernel<<<(Bn * Tn * Hn + 7) / 8, 256>>>(r_k, gn_w, gn_b);

    // 10. output projection
    {
        Jobs J;
        J.j[0] = { p_y, p_wts + OFF_Wo, outp, nullptr, nullptr, nullptr, 0 };
        J.j[1] = J.j[0]; J.j[2] = J.j[0];
        gemmTC<128><<<dim3(8, 16, 1), 256>>>(J, Cn, Cn);
    }
}

// round 4
// speedup vs baseline: 4.2856x; 1.2640x over previous
#include <cuda_runtime.h>
#include <math.h>
#include <stdint.h>

// Problem dims
#define Bn 2
#define Tn 1024
#define Cn 1024
#define Hn 16
#define Dn 64
#define BTn (Bn * Tn)
#define NTOK (Bn * Tn * Cn)
#define W_LR 64
#define A_LR 64
#define V_LR 64
#define G_LR 160
#define DECAY_SCALE (-0.6065306597126334f)
#define GN_EPS (64.0f * 1e-5f)
#define SS 8

// tf32 weight scratch offsets
#define OFF_Wr 0
#define OFF_Wk 1048576
#define OFF_Wv 2097152
#define OFF_Wo 3145728
#define OFF_wA 4194304
#define OFF_aA 4259840
#define OFF_vA 4325376
#define OFF_gA 4390912
#define OFF_wB 4554752
#define OFF_aB 4620288
#define OFF_vB 4685824
#define OFF_gB 4751360
#define WTS_TOTAL 4915200

// ---------------- scratch (__device__ globals) -----------------------------
__device__ float g_xr[NTOK], g_xw[NTOK], g_xk[NTOK], g_xv[NTOK], g_xa[NTOK], g_xg[NTOK];
__device__ float g_r[NTOK], g_k0[NTOK], g_v[NTOK], g_w[NTOK], g_a[NTOK], g_g[NTOK];
__device__ float g_kf[NTOK];
__device__ float g_m[NTOK], g_ad[NTOK], g_rd[NTOK], g_bb[NTOK];
__device__ float g_rb[BTn * Hn], g_rk[BTn * Hn];
__device__ float g_osc[NTOK], g_y[NTOK];
__device__ float g_tmpW[BTn * W_LR], g_tmpA[BTn * A_LR], g_tmpV[BTn * V_LR], g_tmpG[BTn * G_LR];
__device__ float g_wts[WTS_TOTAL];

// ---------------- helpers --------------------------------------------------
__device__ __forceinline__ float sigmoidf_(float x) { return 1.f / (1.f + expf(-x)); }

__device__ __forceinline__ float to_tf32(float x) {
    uint32_t u;
    asm("cvt.rna.tf32.f32 %0, %1;" : "=r"(u) : "f"(x));
    return __uint_as_float(u);
}

__device__ __forceinline__ void cpasync16(void* smem, const void* gptr, int srcbytes) {
    uint32_t s = (uint32_t)__cvta_generic_to_shared(smem);
    asm volatile("cp.async.ca.shared.global [%0], [%1], 16, %2;" :: "r"(s), "l"(gptr), "r"(srcbytes));
}
__device__ __forceinline__ void cpasync4(void* smem, const void* gptr) {
    uint32_t s = (uint32_t)__cvta_generic_to_shared(smem);
    asm volatile("cp.async.ca.shared.global [%0], [%1], 4;" :: "r"(s), "l"(gptr));
}
__device__ __forceinline__ void cpcommit() { asm volatile("cp.async.commit_group;"); }
__device__ __forceinline__ void cpwait1() { asm volatile("cp.async.wait_group 1;"); }
__device__ __forceinline__ void cpwait0() { asm volatile("cp.async.wait_group 0;"); }

__device__ __forceinline__ float2 ffma2(float2 a, float2 b, float2 c) {
    unsigned long long ua = *(unsigned long long*)&a;
    unsigned long long ub = *(unsigned long long*)&b;
    unsigned long long uc = *(unsigned long long*)&c;
    unsigned long long ud;
    asm("fma.rn.f32x2 %0, %1, %2, %3;" : "=l"(ud) : "l"(ua), "l"(ub), "l"(uc));
    return *(float2*)&ud;
}
__device__ __forceinline__ float2 fmul2(float2 a, float2 b) {
    unsigned long long ua = *(unsigned long long*)&a;
    unsigned long long ub = *(unsigned long long*)&b;
    unsigned long long ud;
    asm("mul.rn.f32x2 %0, %1, %2;" : "=l"(ud) : "l"(ua), "l"(ub));
    return *(float2*)&ud;
}

__device__ __forceinline__ void mma_tf32(float* d, const uint32_t* a, const uint32_t* b) {
    asm volatile(
        "mma.sync.aligned.m16n8k8.row.col.f32.tf32.tf32.f32 "
        "{%0,%1,%2,%3}, {%4,%5,%6,%7}, {%8,%9}, {%0,%1,%2,%3};"
        : "+f"(d[0]), "+f"(d[1]), "+f"(d[2]), "+f"(d[3])
        : "r"(a[0]), "r"(a[1]), "r"(a[2]), "r"(a[3]), "r"(b[0]), "r"(b[1]));
}

// ---------------- mix + weight tf32 conversion (one launch) ----------------
__global__ void mixcvt_kernel(const float* __restrict__ hs, const float* __restrict__ xmix,
                              const float* __restrict__ Wr, const float* __restrict__ Wk,
                              const float* __restrict__ Wv, const float* __restrict__ Wo,
                              const float* __restrict__ wA, const float* __restrict__ aA,
                              const float* __restrict__ vA, const float* __restrict__ gA,
                              const float* __restrict__ wB, const float* __restrict__ aB,
                              const float* __restrict__ vB, const float* __restrict__ gB) {
    int idx = blockIdx.x * blockDim.x + threadIdx.x;
    if (idx < NTOK) {
        int c = idx & (Cn - 1);
        int t = (idx / Cn) & (Tn - 1);
        float h = hs[idx];
        float prev = (t == 0) ? 0.f : hs[idx - Cn];
        float d = prev - h;
        g_xr[idx] = to_tf32(fmaf(d, xmix[0 * Cn + c], h));
        g_xw[idx] = to_tf32(fmaf(d, xmix[1 * Cn + c], h));
        g_xk[idx] = to_tf32(fmaf(d, xmix[2 * Cn + c], h));
        g_xv[idx] = to_tf32(fmaf(d, xmix[3 * Cn + c], h));
        g_xa[idx] = to_tf32(fmaf(d, xmix[4 * Cn + c], h));
        g_xg[idx] = to_tf32(fmaf(d, xmix[5 * Cn + c], h));
    } else {
        int j = idx - NTOK;
        if (j >= WTS_TOTAL) return;
        float v;
        if (j < OFF_Wk)      v = Wr[j - OFF_Wr];
        else if (j < OFF_Wv) v = Wk[j - OFF_Wk];
        else if (j < OFF_Wo) v = Wv[j - OFF_Wv];
        else if (j < OFF_wA) v = Wo[j - OFF_Wo];
        else if (j < OFF_aA) v = wA[j - OFF_wA];
        else if (j < OFF_vA) v = aA[j - OFF_aA];
        else if (j < OFF_gA) v = vA[j - OFF_vA];
        else if (j < OFF_wB) v = gA[j - OFF_gA];
        else if (j < OFF_aB) v = wB[j - OFF_wB];
        else if (j < OFF_vB) v = aB[j - OFF_aB];
        else if (j < OFF_gB) v = vB[j - OFF_vB];
        else                 v = gB[j - OFF_gB];
        g_wts[j] = to_tf32(v);
    }
}

// ---------------- tensor-core tf32 GEMM (per-job N,K) ----------------------
// epi: 0 plain, 1 tanh+tf32, 2 sigmoid+tf32, 3 sigmoid(x+bias),
//      4 DECAY*sigmoid(x+bias), 5 lerp p1+(sig(x+bias))*(p2-p1), 6 tf32
struct Job {
    const float* A; const float* W; float* O;
    const float* bias; const float* p1; const float* p2;
    int epi; int N; int K;
};
struct Jobs { Job j[4]; };

template <int BN>
__global__ __launch_bounds__(256) void gemmTC(Jobs jobs) {
    constexpr int WARPS_N = BN / 32;
    constexpr int WARPS_M = 8 / WARPS_N;
    constexpr int WM = 128 / WARPS_M;
    constexpr int MF = WM / 16;

    __shared__ float As[2][128][20];
    __shared__ float Bs[2][BN][20];

    Job jb = jobs.j[blockIdx.z];
    const int N = jb.N, K = jb.K;
    const int row0 = blockIdx.y * 128;
    const int col0 = blockIdx.x * BN;
    if (col0 >= N) return;  // uniform early exit, before any barrier
    const int tid = threadIdx.x;
    const int wid = tid >> 5, lane = tid & 31;
    const int wm = wid % WARPS_M, wn = wid / WARPS_M;
    const int mbase = wm * WM, nbase = wn * 32;
    const int g = lane >> 2, q = lane & 3;
    const int arow = tid >> 2, ac4 = (tid & 3) * 4;

    float acc[MF][4][4];
#pragma unroll
    for (int i = 0; i < MF; i++)
#pragma unroll
        for (int j2 = 0; j2 < 4; j2++)
#pragma unroll
            for (int k2 = 0; k2 < 4; k2++) acc[i][j2][k2] = 0.f;

    const int nk = K >> 4;

    {
        const float* Ag = jb.A + (size_t)(row0 + arow) * K + ac4;
        cpasync16(&As[0][arow][ac4], Ag, 16);
        cpasync16(&As[0][arow + 64][ac4], Ag + (size_t)64 * K, 16);
        int bn0 = col0 + arow;
        const float* Bg = jb.W + (size_t)bn0 * K + ac4;
        cpasync16(&Bs[0][arow][ac4], Bg, (bn0 < N) ? 16 : 0);
        if (BN == 128)
            cpasync16(&Bs[0][arow + 64][ac4], Bg + (size_t)64 * K, (bn0 + 64 < N) ? 16 : 0);
        cpcommit();
    }

    for (int kt = 0; kt < nk; kt++) {
        const int buf = kt & 1;
        if (kt + 1 < nk) {
            const int nb = buf ^ 1;
            const float* Ag = jb.A + (size_t)(row0 + arow) * K + (kt + 1) * 16 + ac4;
            cpasync16(&As[nb][arow][ac4], Ag, 16);
            cpasync16(&As[nb][arow + 64][ac4], Ag + (size_t)64 * K, 16);
            int bn0 = col0 + arow;
            const float* Bg = jb.W + (size_t)bn0 * K + (kt + 1) * 16 + ac4;
            cpasync16(&Bs[nb][arow][ac4], Bg, (bn0 < N) ? 16 : 0);
            if (BN == 128)
                cpasync16(&Bs[nb][arow + 64][ac4], Bg + (size_t)64 * K, (bn0 + 64 < N) ? 16 : 0);
            cpcommit();
            cpwait1();
        } else {
            cpwait0();
        }
        __syncthreads();

        const uint32_t* Au = (const uint32_t*)&As[buf][0][0];
        const uint32_t* Bu = (const uint32_t*)&Bs[buf][0][0];
#pragma unroll
        for (int ks = 0; ks < 16; ks += 8) {
            uint32_t af[MF][4], bf[4][2];
#pragma unroll
            for (int mf = 0; mf < MF; mf++) {
                int m = mbase + mf * 16 + g;
                af[mf][0] = Au[m * 20 + ks + q];
                af[mf][1] = Au[(m + 8) * 20 + ks + q];
                af[mf][2] = Au[m * 20 + ks + q + 4];
                af[mf][3] = Au[(m + 8) * 20 + ks + q + 4];
            }
#pragma unroll
            for (int nf = 0; nf < 4; nf++) {
                int n = nbase + nf * 8 + g;
                bf[nf][0] = Bu[n * 20 + ks + q];
                bf[nf][1] = Bu[n * 20 + ks + q + 4];
            }
#pragma unroll
            for (int mf = 0; mf < MF; mf++)
#pragma unroll
                for (int nf = 0; nf < 4; nf++) mma_tf32(acc[mf][nf], af[mf], bf[nf]);
        }
        __syncthreads();
    }

    const int epi = jb.epi;
#pragma unroll
    for (int mf = 0; mf < MF; mf++) {
#pragma unroll
        for (int nf = 0; nf < 4; nf++) {
            int r0 = row0 + mbase + mf * 16 + g;
            int c = col0 + nbase + nf * 8 + 2 * q;
            if (c >= N) continue;
#pragma unroll
            for (int rr = 0; rr < 2; rr++) {
                int r = r0 + rr * 8;
                float x0 = acc[mf][nf][rr * 2 + 0];
                float x1 = acc[mf][nf][rr * 2 + 1];
                float y0, y1;
                if (epi == 0) { y0 = x0; y1 = x1; }
                else if (epi == 6) { y0 = to_tf32(x0); y1 = to_tf32(x1); }
                else if (epi == 1) { y0 = to_tf32(tanhf(x0)); y1 = to_tf32(tanhf(x1)); }
                else if (epi == 2) { y0 = to_tf32(sigmoidf_(x0)); y1 = to_tf32(sigmoidf_(x1)); }
                else if (epi == 3) {
                    y0 = sigmoidf_(x0 + __ldg(jb.bias + c));
                    y1 = sigmoidf_(x1 + __ldg(jb.bias + c + 1));
                } else if (epi == 4) {
                    y0 = DECAY_SCALE * sigmoidf_(x0 + __ldg(jb.bias + c));
                    y1 = DECAY_SCALE * sigmoidf_(x1 + __ldg(jb.bias + c + 1));
                } else {
                    size_t i0 = (size_t)r * N + c;
                    float s0 = sigmoidf_(x0 + __ldg(jb.bias + c));
                    float s1 = sigmoidf_(x1 + __ldg(jb.bias + c + 1));
                    float a0 = jb.p1[i0], b0 = jb.p2[i0];
                    float a1 = jb.p1[i0 + 1], b1 = jb.p2[i0 + 1];
                    y0 = fmaf(s0, b0 - a0, a0);
                    y1 = fmaf(s1, b1 - a1, a1);
                }
                *(float2*)(jb.O + (size_t)r * N + c) = make_float2(y0, y1);
            }
        }
    }
}

// ---------------- prep: kk-normalize, k-final, scan precomputes ------------
__global__ void prep_kernel(const float* __restrict__ k_k, const float* __restrict__ k_a) {
    int gid = blockIdx.x * (blockDim.x >> 5) + (threadIdx.x >> 5);
    int lane = threadIdx.x & 31;
    if (gid >= BTn * Hn) return;
    int bt = gid >> 4, h = gid & 15;
    size_t base = (size_t)bt * Cn + h * Dn;
    int c0 = h * Dn + lane, c1 = c0 + 32;

    float k0a = g_k0[base + lane], k0b = g_k0[base + lane + 32];
    float q0 = k0a * k_k[c0], q1 = k0b * k_k[c1];
    float s = q0 * q0 + q1 * q1;
#pragma unroll
    for (int off = 16; off > 0; off >>= 1) s += __shfl_xor_sync(0xffffffffu, s, off);
    float inv = 1.f / fmaxf(sqrtf(s), 1e-12f);
    float kk0 = q0 * inv, kk1 = q1 * inv;

    float a0 = g_a[base + lane], a1 = g_a[base + lane + 32];
    float kf0 = k0a * (1.f + (a0 - 1.f) * k_a[c0]);
    float kf1 = k0b * (1.f + (a1 - 1.f) * k_a[c1]);
    float m0 = expf(g_w[base + lane]), m1 = expf(g_w[base + lane + 32]);
    float r0 = g_r[base + lane], r1 = g_r[base + lane + 32];
    float b0 = kk0 * a0, b1 = kk1 * a1;

    g_m[base + lane] = m0;          g_m[base + lane + 32] = m1;
    g_ad[base + lane] = -kk0 * m0;  g_ad[base + lane + 32] = -kk1 * m1;
    g_rd[base + lane] = r0 * m0;    g_rd[base + lane + 32] = r1 * m1;
    g_bb[base + lane] = b0;         g_bb[base + lane + 32] = b1;
    g_kf[base + lane] = kf0;        g_kf[base + lane + 32] = kf1;

    float rb = r0 * b0 + r1 * b1;
    float rk = r0 * kf0 + r1 * kf1;
#pragma unroll
    for (int off = 16; off > 0; off >>= 1) {
        rb += __shfl_xor_sync(0xffffffffu, rb, off);
        rk += __shfl_xor_sync(0xffffffffu, rk, off);
    }
    if (lane == 0) { g_rb[gid] = rb; g_rk[gid] = rk; }
}

// ---------------- sequential WKV7 scan, column-parallel ---------------------
// 64 blocks: block = (b,h,half). 128 threads: warp w covers 8 columns,
// lane = dq*8 + c, dq owns d in [dq*16, dq*16+16).  Column e = half*32+w*8+c.
__global__ __launch_bounds__(128, 1) void scan_kernel(float* __restrict__ out) {
    const int bx = blockIdx.x;
    const int bh = bx >> 1, half = bx & 1;
    const int b = bh >> 4, h = bh & 15;
    const int tid = threadIdx.x;
    const int wid = tid >> 5, lane = tid & 31;
    const int c = lane & 7, dq = lane >> 3;
    const int e = half * 32 + wid * 8 + c;
    const int d0 = dq * 16;
    const int bT0 = b * Tn;

    __shared__ float sb[2][5][SS][64];
    __shared__ float sv[2][SS][32];
    __shared__ float sc[2][2][SS];

    float2 S[8];
#pragma unroll
    for (int i = 0; i < 8; i++) S[i] = make_float2(0.f, 0.f);

    const float* aps[5] = { g_m, g_ad, g_rd, g_bb, g_kf };

    auto stage = [&](int ss, int bufI) {
#pragma unroll
        for (int j = tid; j < 704; j += 128) {
            if (j < 640) {
                int arr = j >> 7, rem = j & 127, s = rem >> 4, f4 = rem & 15;
                const float* src = aps[arr] + ((size_t)(bT0 + ss * SS + s)) * Cn + h * Dn + f4 * 4;
                cpasync16(&sb[bufI][arr][s][f4 * 4], src, 16);
            } else {
                int jj = j - 640;
                int s = jj >> 3, f4 = jj & 7;
                const float* src = g_v + ((size_t)(bT0 + ss * SS + s)) * Cn + h * Dn + half * 32 + f4 * 4;
                cpasync16(&sv[bufI][s][f4 * 4], src, 16);
            }
        }
        if (tid < 16) {
            int arr = tid >> 3, s = tid & 7;
            const float* src = (arr ? g_rk : g_rb) + (size_t)(bT0 + ss * SS + s) * Hn + h;
            cpasync4(&sc[bufI][arr][s], src);
        }
        cpcommit();
    };

    stage(0, 0);

    for (int ss = 0; ss < Tn / SS; ss++) {
        const int cur = ss & 1;
        cpwait0();
        __syncthreads();
        if (ss + 1 < Tn / SS) stage(ss + 1, cur ^ 1);

#pragma unroll 2
        for (int s = 0; s < SS; s++) {
            // phase 1: dot operands only
            float4 ad4[4], rd4[4];
#pragma unroll
            for (int i = 0; i < 4; i++) {
                ad4[i] = *(const float4*)&sb[cur][1][s][d0 + i * 4];
                rd4[i] = *(const float4*)&sb[cur][2][s][d0 + i * 4];
            }
            const float2* ad2 = (const float2*)ad4;
            const float2* rd2 = (const float2*)rd4;

            float2 tA = make_float2(0.f, 0.f), tB = make_float2(0.f, 0.f);
            float2 rA = make_float2(0.f, 0.f), rB = make_float2(0.f, 0.f);
#pragma unroll
            for (int i = 0; i < 8; i += 2) {
                tA = ffma2(ad2[i], S[i], tA);
                tB = ffma2(ad2[i + 1], S[i + 1], tB);
                rA = ffma2(rd2[i], S[i], rA);
                rB = ffma2(rd2[i + 1], S[i + 1], rB);
            }
            float ta = (tA.x + tB.x) + (tA.y + tB.y);
            float ro = (rA.x + rB.x) + (rA.y + rB.y);

            // phase 2 loads issued before shfl to overlap shuffle latency
            float4 m4[4], b4[4], k4[4];
#pragma unroll
            for (int i = 0; i < 4; i++) {
                m4[i] = *(const float4*)&sb[cur][0][s][d0 + i * 4];
                b4[i] = *(const float4*)&sb[cur][3][s][d0 + i * 4];
                k4[i] = *(const float4*)&sb[cur][4][s][d0 + i * 4];
            }
            float v = sv[cur][s][wid * 8 + c];
            float rb = sc[cur][0][s], rk = sc[cur][1][s];

            ta += __shfl_xor_sync(0xffffffffu, ta, 8);
            ro += __shfl_xor_sync(0xffffffffu, ro, 8);
            ta += __shfl_xor_sync(0xffffffffu, ta, 16);
            ro += __shfl_xor_sync(0xffffffffu, ro, 16);

            const float2* m2 = (const float2*)m4;
            const float2* b2 = (const float2*)b4;
            const float2* k2 = (const float2*)k4;
            float2 ta2 = make_float2(ta, ta), v2 = make_float2(v, v);
#pragma unroll
            for (int i = 0; i < 8; i++) {
                float2 t1 = fmul2(k2[i], v2);
                t1 = ffma2(b2[i], ta2, t1);
                S[i] = ffma2(m2[i], S[i], t1);
            }
            if (dq == 0) {
                out[((size_t)(bT0 + ss * SS + s)) * Cn + h * Dn + e] =
                    fmaf(rb, ta, fmaf(rk, v, ro));
            }
        }
    }
}

// ---------------- GroupNorm + corr + gate ----------------------------------
__global__ void post_kernel(const float* __restrict__ r_k, const float* __restrict__ gn_w,
                            const float* __restrict__ gn_b) {
    int gid = blockIdx.x * (blockDim.x >> 5) + (threadIdx.x >> 5);
    int lane = threadIdx.x & 31;
    if (gid >= Bn * Tn * Hn) return;
    size_t base = (size_t)(gid >> 4) * Cn + (gid & 15) * Dn;
    int h = gid & 15;
    int c0 = h * Dn + lane, c1 = c0 + 32;
    float o0 = g_osc[base + lane], o1 = g_osc[base + lane + 32];
    float s1 = o0 + o1;
    float s2 = o0 * o0 + o1 * o1;
    float rr0 = g_r[base + lane], rr1 = g_r[base + lane + 32];
    float kk0 = g_kf[base + lane], kk1 = g_kf[base + lane + 32];
    float dp = rr0 * kk0 * r_k[c0] + rr1 * kk1 * r_k[c1];
#pragma unroll
    for (int off = 16; off > 0; off >>= 1) {
        s1 += __shfl_xor_sync(0xffffffffu, s1, off);
        s2 += __shfl_xor_sync(0xffffffffu, s2, off);
        dp += __shfl_xor_sync(0xffffffffu, dp, off);
    }
    float mu = s1 * (1.f / 64.f);
    float var = s2 * (1.f / 64.f) - mu * mu;
    float inv = 1.f / sqrtf(var + GN_EPS);
    float v0 = g_v[base + lane], v1 = g_v[base + lane + 32];
    float y0 = ((o0 - mu) * inv * gn_w[c0] + gn_b[c0] + dp * v0) * g_g[base + lane];
    float y1 = ((o1 - mu) * inv * gn_w[c1] + gn_b[c1] + dp * v1) * g_g[base + lane + 32];
    g_y[base + lane] = to_tf32(y0);
    g_y[base + lane + 32] = to_tf32(y1);
}

// ---------------- launch ----------------------------------------------------
extern "C" void kernel_launch(void* const* d_in, const int* in_sizes, int n_in,
                              void* d_out, int out_size) {
    const float* hs     = (const float*)d_in[0];
    const float* vfirst = (const float*)d_in[1];
    const float* xmix   = (const float*)d_in[2];
    const float* k_k    = (const float*)d_in[3];
    const float* k_a    = (const float*)d_in[4];
    const float* r_k    = (const float*)d_in[5];
    const float* W_r    = (const float*)d_in[6];
    const float* W_k    = (const float*)d_in[7];
    const float* W_v    = (const float*)d_in[8];
    const float* W_o    = (const float*)d_in[9];
    const float* w_A    = (const float*)d_in[10];
    const float* w_B    = (const float*)d_in[11];
    const float* w_b    = (const float*)d_in[12];
    const float* a_A    = (const float*)d_in[13];
    const float* a_B    = (const float*)d_in[14];
    const float* a_b    = (const float*)d_in[15];
    const float* v_A    = (const float*)d_in[16];
    const float* v_B    = (const float*)d_in[17];
    const float* v_b    = (const float*)d_in[18];
    const float* g_Ain  = (const float*)d_in[19];
    const float* g_Bin  = (const float*)d_in[20];
    const float* gn_w   = (const float*)d_in[21];
    const float* gn_b   = (const float*)d_in[22];
    float* outp = (float*)d_out;

    float *p_xr, *p_xw, *p_xk, *p_xv, *p_xa, *p_xg;
    float *p_r, *p_k0, *p_v, *p_w, *p_a, *p_g, *p_osc, *p_y;
    float *p_tmpW, *p_tmpA, *p_tmpV, *p_tmpG, *p_wts;
    cudaGetSymbolAddress((void**)&p_xr, g_xr);
    cudaGetSymbolAddress((void**)&p_xw, g_xw);
    cudaGetSymbolAddress((void**)&p_xk, g_xk);
    cudaGetSymbolAddress((void**)&p_xv, g_xv);
    cudaGetSymbolAddress((void**)&p_xa, g_xa);
    cudaGetSymbolAddress((void**)&p_xg, g_xg);
    cudaGetSymbolAddress((void**)&p_r, g_r);
    cudaGetSymbolAddress((void**)&p_k0, g_k0);
    cudaGetSymbolAddress((void**)&p_v, g_v);
    cudaGetSymbolAddress((void**)&p_w, g_w);
    cudaGetSymbolAddress((void**)&p_a, g_a);
    cudaGetSymbolAddress((void**)&p_g, g_g);
    cudaGetSymbolAddress((void**)&p_osc, g_osc);
    cudaGetSymbolAddress((void**)&p_y, g_y);
    cudaGetSymbolAddress((void**)&p_tmpW, g_tmpW);
    cudaGetSymbolAddress((void**)&p_tmpA, g_tmpA);
    cudaGetSymbolAddress((void**)&p_tmpV, g_tmpV);
    cudaGetSymbolAddress((void**)&p_tmpG, g_tmpG);
    cudaGetSymbolAddress((void**)&p_wts, g_wts);

    // 1. mix + weight tf32 conversion
    {
        int total = NTOK + WTS_TOTAL;
        mixcvt_kernel<<<(total + 255) / 256, 256>>>(hs, xmix, W_r, W_k, W_v, W_o,
                                                    w_A, a_A, v_A, g_Ain,
                                                    w_B, a_B, v_B, g_Bin);
    }

    // 2. r, k0, v0 (z=3)
    {
        Jobs J;
        J.j[0] = { p_xr, p_wts + OFF_Wr, p_r,  nullptr, nullptr, nullptr, 0, Cn, Cn };
        J.j[1] = { p_xk, p_wts + OFF_Wk, p_k0, nullptr, nullptr, nullptr, 0, Cn, Cn };
        J.j[2] = { p_xv, p_wts + OFF_Wv, p_v,  nullptr, nullptr, nullptr, 0, Cn, Cn };
        J.j[3] = J.j[0];
        gemmTC<128><<<dim3(8, 16, 3), 256>>>(J);
    }
    // 3. LoRA stage 1 for w,a,v,g (z=4)
    {
        Jobs J;
        J.j[0] = { p_xw, p_wts + OFF_wA, p_tmpW, nullptr, nullptr, nullptr, 1, W_LR, Cn };
        J.j[1] = { p_xa, p_wts + OFF_aA, p_tmpA, nullptr, nullptr, nullptr, 6, A_LR, Cn };
        J.j[2] = { p_xv, p_wts + OFF_vA, p_tmpV, nullptr, nullptr, nullptr, 6, V_LR, Cn };
        J.j[3] = { p_xg, p_wts + OFF_gA, p_tmpG, nullptr, nullptr, nullptr, 2, G_LR, Cn };
        gemmTC<64><<<dim3(3, 16, 4), 256>>>(J);
    }
    // 4. LoRA stage 2 for w,a,v,g (z=4)
    {
        Jobs J;
        J.j[0] = { p_tmpW, p_wts + OFF_wB, p_w, w_b, nullptr, nullptr, 4, Cn, W_LR };
        J.j[1] = { p_tmpA, p_wts + OFF_aB, p_a, a_b, nullptr, nullptr, 3, Cn, A_LR };
        J.j[2] = { p_tmpV, p_wts + OFF_vB, p_v, v_b, p_v, vfirst, 5, Cn, V_LR };
        J.j[3] = { p_tmpG, p_wts + OFF_gB, p_g, nullptr, nullptr, nullptr, 0, Cn, G_LR };
        gemmTC<128><<<dim3(8, 16, 4), 256>>>(J);
    }
    // 5. prep (kk norm, k final, scan precomputes)
    prep_kernel<<<(BTn * Hn + 7) / 8, 256>>>(k_k, k_a);

    // 6. sequential scan
    scan_kernel<<<Bn * Hn * 2, 128>>>(p_osc);

    // 7. groupnorm + corr + gate
    post_kernel<<<(Bn * Tn * Hn + 7) / 8, 256>>>(r_k, gn_w, gn_b);

    // 8. output projection
    {
        Jobs J;
        J.j[0] = { p_y, p_wts + OFF_Wo, outp, nullptr, nullptr, nullptr, 0, Cn, Cn };
        J.j[1] = J.j[0]; J.j[2] = J.j[0]; J.j[3] = J.j[0];
        gemmTC<128><<<dim3(8, 16, 1), 256>>>(J);
    }
}